// round 2
// baseline (speedup 1.0000x reference)
#include <cuda_runtime.h>
#include <math.h>

#define N_NODES 100000
#define N_EDGES 1600000
#define N_QUERY 500000
#define F_IN 7
#define HID 128
#define EMB 64

// ---------------- scratch (device globals; no allocations allowed) ----------------
__device__ float g_deg[N_NODES];
__device__ float g_dinv[N_NODES];
__device__ float g_bufA[N_NODES * HID];
__device__ float g_bufB[N_NODES * HID];
__device__ float g_z[N_NODES * EMB];

// ---------------- degree / normalization ----------------
__global__ void k_deg_init() {
    int i = blockIdx.x * blockDim.x + threadIdx.x;
    if (i < N_NODES) g_deg[i] = 1.0f;  // +1 self loop
}

__global__ void k_deg_count(const int* __restrict__ ei) {
    int e = blockIdx.x * blockDim.x + threadIdx.x;
    if (e < N_EDGES) atomicAdd(&g_deg[ei[N_EDGES + e]], 1.0f);
}

__global__ void k_dinv() {
    int i = blockIdx.x * blockDim.x + threadIdx.x;
    if (i < N_NODES) g_dinv[i] = rsqrtf(g_deg[i]);
}

// ---------------- layer-1 input matmul: h = x @ W1  ([100k,7]@[7,128]) ----------------
__global__ void k_mm_in(const float* __restrict__ x, const float* __restrict__ W,
                        float* __restrict__ out) {
    __shared__ float sW[F_IN * HID];
    int tid = threadIdx.x;
    for (int i = tid; i < F_IN * HID; i += blockDim.x) sW[i] = W[i];
    __syncthreads();
    int idx = blockIdx.x * blockDim.x + tid;
    if (idx >= N_NODES * HID) return;
    int node = idx >> 7, j = idx & 127;
    float acc = 0.f;
#pragma unroll
    for (int k = 0; k < F_IN; k++) acc = fmaf(x[node * F_IN + k], sW[k * HID + j], acc);
    out[idx] = acc;
}

// ---------------- self-loop init: agg = h * dinv^2 ----------------
__global__ void k_selfloop(const float4* __restrict__ h4, float4* __restrict__ agg4) {
    int i = blockIdx.x * blockDim.x + threadIdx.x;
    if (i >= N_NODES * HID / 4) return;
    int node = i >> 5;  // 32 float4 per node row
    float d = g_dinv[node];
    float s = d * d;
    float4 v = h4[i];
    agg4[i] = make_float4(v.x * s, v.y * s, v.z * s, v.w * s);
}

// ---------------- edge scatter: agg[dst] += h[src] * dinv[src]*dinv[dst] ----------------
// One warp per edge; lane l handles float4 chunk l. Vector red (sm_90+) quarters atomic op count.
__global__ void k_scatter(const float* __restrict__ h, const int* __restrict__ ei,
                          float* __restrict__ agg) {
    int t = blockIdx.x * blockDim.x + threadIdx.x;
    int e = t >> 5;
    int lane = t & 31;
    if (e >= N_EDGES) return;
    int s = ei[e];
    int d = ei[N_EDGES + e];
    float norm = g_dinv[s] * g_dinv[d];
    float4 v = *(const float4*)(h + (size_t)s * HID + lane * 4);
    float* p = agg + (size_t)d * HID + lane * 4;
    asm volatile("red.global.add.v4.f32 [%0], {%1,%2,%3,%4};"
                 :: "l"(p), "f"(v.x * norm), "f"(v.y * norm), "f"(v.z * norm), "f"(v.w * norm)
                 : "memory");
}

// ---------------- bias + relu (elementwise, float4) ----------------
__global__ void k_bias_relu(const float4* __restrict__ in, const float* __restrict__ b,
                            float4* __restrict__ out) {
    int i = blockIdx.x * blockDim.x + threadIdx.x;
    if (i >= N_NODES * HID / 4) return;
    float4 bv = ((const float4*)b)[i & 31];
    float4 v = in[i];
    out[i] = make_float4(fmaxf(v.x + bv.x, 0.f), fmaxf(v.y + bv.y, 0.f),
                         fmaxf(v.z + bv.z, 0.f), fmaxf(v.w + bv.w, 0.f));
}

// ---------------- generic K=128 GEMM: C[M,N] = A[M,128] @ B[128,N] (+bias) ----------------
// 32-row tile per block, 256 threads, k-tiling TK=32.
template <int N, bool BIAS>
__global__ void gemm_k128(const float* __restrict__ A, const float* __restrict__ B,
                          const float* __restrict__ bias, float* __restrict__ C) {
    constexpr int TK = 32;
    constexpr int MR = 32;
    constexpr int CG = N / 4;         // col groups (float4 per thread)
    constexpr int RT = 256 / CG;      // row-thread groups
    constexpr int RPT = MR / RT;      // rows per thread
    __shared__ float sA[MR][TK];
    __shared__ float sB[TK][N];
    const int tid = threadIdx.x;
    const int row0 = blockIdx.x * MR;
    const int cg = tid % CG;
    const int rt = tid / CG;

    float acc[RPT][4];
#pragma unroll
    for (int i = 0; i < RPT; i++)
#pragma unroll
        for (int j = 0; j < 4; j++) acc[i][j] = 0.f;

    for (int kt = 0; kt < 128; kt += TK) {
        {   // A tile: 32x32 = 256 float4, one per thread
            int r = tid >> 3, k4 = tid & 7;
            *(float4*)&sA[r][k4 * 4] =
                *(const float4*)&A[(size_t)(row0 + r) * 128 + kt + k4 * 4];
        }
        for (int i = tid; i < TK * N / 4; i += 256) {
            int k = i / (N / 4), j4 = i % (N / 4);
            *(float4*)&sB[k][j4 * 4] = *(const float4*)&B[(size_t)(kt + k) * N + j4 * 4];
        }
        __syncthreads();
#pragma unroll
        for (int k = 0; k < TK; k++) {
            float4 b = *(const float4*)&sB[k][cg * 4];
#pragma unroll
            for (int i = 0; i < RPT; i++) {
                float a = sA[rt * RPT + i][k];
                acc[i][0] = fmaf(a, b.x, acc[i][0]);
                acc[i][1] = fmaf(a, b.y, acc[i][1]);
                acc[i][2] = fmaf(a, b.z, acc[i][2]);
                acc[i][3] = fmaf(a, b.w, acc[i][3]);
            }
        }
        __syncthreads();
    }
    float4 bv = make_float4(0.f, 0.f, 0.f, 0.f);
    if (BIAS) bv = *(const float4*)&bias[cg * 4];
#pragma unroll
    for (int i = 0; i < RPT; i++) {
        float4 o = make_float4(acc[i][0] + bv.x, acc[i][1] + bv.y,
                               acc[i][2] + bv.z, acc[i][3] + bv.w);
        *(float4*)&C[(size_t)(row0 + rt * RPT + i) * N + cg * 4] = o;
    }
}

// ---------------- decoder: 128 queries per block, 3-stage smem-resident MLP ----------------
// smem: zc[128][128] | W (Wd1 then Wd2) [128][128] | C1[128][128]  = 192 KB dynamic
__global__ __launch_bounds__(512) void k_decoder(
    const float* __restrict__ z, const int* __restrict__ qe,
    const float* __restrict__ Wd1, const float* __restrict__ bd1,
    const float* __restrict__ Wd2, const float* __restrict__ bd2,
    const float* __restrict__ Wd3, const float* __restrict__ bd3,
    float* __restrict__ out) {
    extern __shared__ float smem[];
    float* s_zc = smem;            // [128*128]; reused as C2 [128*64] in stage 2
    float* s_w  = smem + 16384;    // weights
    float* s_c1 = smem + 32768;    // [128*128]
    __shared__ float s_wd3[EMB];
    __shared__ float s_b1[HID];
    __shared__ float s_b2[EMB];

    const int tid = threadIdx.x;
    const int q0 = blockIdx.x * 128;

    // load Wd1 + small vectors
    for (int i = tid; i < HID * HID / 4; i += 512)
        ((float4*)s_w)[i] = ((const float4*)Wd1)[i];
    if (tid < HID) s_b1[tid] = bd1[tid];
    if (tid < EMB) { s_b2[tid] = bd2[tid]; s_wd3[tid] = Wd3[tid]; }

    // gather zc[q] = concat(z[qe0[q]], z[qe1[q]]): 4 threads per query
    {
        int q = tid >> 2, p = tid & 3;
        int qi = q0 + q;
        float4* dst = (float4*)(s_zc + q * 128 + p * 32);
        if (qi < N_QUERY) {
            int node = (p < 2) ? qe[qi] : qe[N_QUERY + qi];
            const float4* src = (const float4*)(z + (size_t)node * EMB + (p & 1) * 32);
#pragma unroll
            for (int i = 0; i < 8; i++) dst[i] = src[i];
        } else {
#pragma unroll
            for (int i = 0; i < 8; i++) dst[i] = make_float4(0.f, 0.f, 0.f, 0.f);
        }
    }
    __syncthreads();

    // stage 1: C1 = relu(zc @ Wd1 + b1)  [128x128]; thread tile 4 rows x 8 cols
    {
        const int cg = tid & 15, rt = tid >> 4;
        float acc[4][8];
#pragma unroll
        for (int i = 0; i < 4; i++)
#pragma unroll
            for (int j = 0; j < 8; j++) acc[i][j] = 0.f;
#pragma unroll 2
        for (int k = 0; k < HID; k++) {
            float4 b0 = *(const float4*)&s_w[k * HID + cg * 8];
            float4 b1v = *(const float4*)&s_w[k * HID + cg * 8 + 4];
#pragma unroll
            for (int i = 0; i < 4; i++) {
                float a = s_zc[(rt * 4 + i) * HID + k];
                acc[i][0] = fmaf(a, b0.x, acc[i][0]);
                acc[i][1] = fmaf(a, b0.y, acc[i][1]);
                acc[i][2] = fmaf(a, b0.z, acc[i][2]);
                acc[i][3] = fmaf(a, b0.w, acc[i][3]);
                acc[i][4] = fmaf(a, b1v.x, acc[i][4]);
                acc[i][5] = fmaf(a, b1v.y, acc[i][5]);
                acc[i][6] = fmaf(a, b1v.z, acc[i][6]);
                acc[i][7] = fmaf(a, b1v.w, acc[i][7]);
            }
        }
        float4 bb0 = *(const float4*)&s_b1[cg * 8];
        float4 bb1 = *(const float4*)&s_b1[cg * 8 + 4];
#pragma unroll
        for (int i = 0; i < 4; i++) {
            int row = rt * 4 + i;
            float4 o0 = make_float4(fmaxf(acc[i][0] + bb0.x, 0.f), fmaxf(acc[i][1] + bb0.y, 0.f),
                                    fmaxf(acc[i][2] + bb0.z, 0.f), fmaxf(acc[i][3] + bb0.w, 0.f));
            float4 o1 = make_float4(fmaxf(acc[i][4] + bb1.x, 0.f), fmaxf(acc[i][5] + bb1.y, 0.f),
                                    fmaxf(acc[i][6] + bb1.z, 0.f), fmaxf(acc[i][7] + bb1.w, 0.f));
            *(float4*)&s_c1[row * HID + cg * 8] = o0;
            *(float4*)&s_c1[row * HID + cg * 8 + 4] = o1;
        }
    }
    __syncthreads();
    // swap weights to Wd2
    for (int i = tid; i < HID * EMB / 4; i += 512)
        ((float4*)s_w)[i] = ((const float4*)Wd2)[i];
    __syncthreads();

    // stage 2: C2 = relu(C1 @ Wd2 + b2) [128x64] -> s_zc; thread tile 4 rows x 4 cols
    {
        const int cg = tid & 15, rt = tid >> 4;
        float acc[4][4];
#pragma unroll
        for (int i = 0; i < 4; i++)
#pragma unroll
            for (int j = 0; j < 4; j++) acc[i][j] = 0.f;
#pragma unroll 2
        for (int k = 0; k < HID; k++) {
            float4 b = *(const float4*)&s_w[k * EMB + cg * 4];
#pragma unroll
            for (int i = 0; i < 4; i++) {
                float a = s_c1[(rt * 4 + i) * HID + k];
                acc[i][0] = fmaf(a, b.x, acc[i][0]);
                acc[i][1] = fmaf(a, b.y, acc[i][1]);
                acc[i][2] = fmaf(a, b.z, acc[i][2]);
                acc[i][3] = fmaf(a, b.w, acc[i][3]);
            }
        }
        float4 bb = *(const float4*)&s_b2[cg * 4];
#pragma unroll
        for (int i = 0; i < 4; i++) {
            int row = rt * 4 + i;
            float4 o = make_float4(fmaxf(acc[i][0] + bb.x, 0.f), fmaxf(acc[i][1] + bb.y, 0.f),
                                   fmaxf(acc[i][2] + bb.z, 0.f), fmaxf(acc[i][3] + bb.w, 0.f));
            *(float4*)&s_zc[row * EMB + cg * 4] = o;
        }
    }
    __syncthreads();

    // stage 3: logits + sigmoid
    if (tid < 128) {
        int qi = q0 + tid;
        if (qi < N_QUERY) {
            float s = bd3[0];
#pragma unroll
            for (int k = 0; k < EMB; k++) s = fmaf(s_zc[tid * EMB + k], s_wd3[k], s);
            out[qi] = 1.0f / (1.0f + expf(-s));
        }
    }
}

// ---------------- launch ----------------
extern "C" void kernel_launch(void* const* d_in, const int* in_sizes, int n_in,
                              void* d_out, int out_size) {
    const float* x   = (const float*)d_in[0];
    const int* ei    = (const int*)d_in[1];
    const int* qe    = (const int*)d_in[2];
    const float* W1  = (const float*)d_in[3];
    const float* b1  = (const float*)d_in[4];
    const float* W2  = (const float*)d_in[5];
    const float* b2  = (const float*)d_in[6];
    const float* Wfc = (const float*)d_in[7];
    const float* bfc = (const float*)d_in[8];
    const float* Wd1 = (const float*)d_in[9];
    const float* bd1 = (const float*)d_in[10];
    const float* Wd2 = (const float*)d_in[11];
    const float* bd2 = (const float*)d_in[12];
    const float* Wd3 = (const float*)d_in[13];
    const float* bd3 = (const float*)d_in[14];
    float* out = (float*)d_out;

    float *pA, *pB, *pZ;
    { void* p; cudaGetSymbolAddress(&p, g_bufA); pA = (float*)p; }
    { void* p; cudaGetSymbolAddress(&p, g_bufB); pB = (float*)p; }
    { void* p; cudaGetSymbolAddress(&p, g_z);    pZ = (float*)p; }

    cudaFuncSetAttribute(k_decoder, cudaFuncAttributeMaxDynamicSharedMemorySize, 196608);

    const int EV = N_NODES * HID / 4;  // float4 elements

    k_deg_init<<<(N_NODES + 255) / 256, 256>>>();
    k_deg_count<<<(N_EDGES + 255) / 256, 256>>>(ei);
    k_dinv<<<(N_NODES + 255) / 256, 256>>>();

    // layer 1
    k_mm_in<<<(N_NODES * HID + 255) / 256, 256>>>(x, W1, pA);
    k_selfloop<<<(EV + 255) / 256, 256>>>((const float4*)pA, (float4*)pB);
    k_scatter<<<(N_EDGES * 32) / 256, 256>>>(pA, ei, pB);
    k_bias_relu<<<(EV + 255) / 256, 256>>>((const float4*)pB, b1, (float4*)pA);

    // layer 2
    gemm_k128<HID, false><<<N_NODES / 32, 256>>>(pA, W2, nullptr, pB);
    k_selfloop<<<(EV + 255) / 256, 256>>>((const float4*)pB, (float4*)pA);
    k_scatter<<<(N_EDGES * 32) / 256, 256>>>(pB, ei, pA);
    k_bias_relu<<<(EV + 255) / 256, 256>>>((const float4*)pA, b2, (float4*)pB);

    // encoder fc
    gemm_k128<EMB, true><<<N_NODES / 32, 256>>>(pB, Wfc, bfc, pZ);

    // decoder
    k_decoder<<<(N_QUERY + 127) / 128, 512, 196608>>>(pZ, qe, Wd1, bd1, Wd2, bd2, Wd3, bd3, out);
}

// round 3
// speedup vs baseline: 1.3719x; 1.3719x over previous
#include <cuda_runtime.h>
#include <math.h>

#define N_NODES 100000
#define N_EDGES 1600000
#define N_QUERY 500000
#define F_IN 7
#define HID 128
#define EMB 64

// ---------------- scratch (device globals; module-load allocations are allowed) --------
__device__ float g_deg[N_NODES];
__device__ float g_dinv[N_NODES];
__device__ float g_bufA[N_NODES * HID];
__device__ float g_bufB[N_NODES * HID];
__device__ float g_bufC[N_NODES * HID];
__device__ float g_z[N_NODES * EMB];
__device__ float g_uv[(size_t)N_NODES * 256];   // [U(128)+b1 | V(128)] per node

// ---------------- degree / normalization ----------------
__global__ void k_deg_init() {
    int i = blockIdx.x * blockDim.x + threadIdx.x;
    if (i < N_NODES) g_deg[i] = 1.0f;  // +1 self loop
}

__global__ void k_deg_count(const int* __restrict__ ei) {
    int e = blockIdx.x * blockDim.x + threadIdx.x;
    if (e < N_EDGES) atomicAdd(&g_deg[ei[N_EDGES + e]], 1.0f);
}

__global__ void k_dinv() {
    int i = blockIdx.x * blockDim.x + threadIdx.x;
    if (i < N_NODES) g_dinv[i] = rsqrtf(g_deg[i]);
}

// ---------------- layer-1 input matmul + fused selfloop init ----------------
// h = x @ W1 ([100k,7]@[7,128]); init = h * dinv^2. One warp per node, float4/thread.
__global__ void k_mm_in(const float* __restrict__ x, const float* __restrict__ W,
                        float* __restrict__ h, float* __restrict__ init) {
    __shared__ float sW[F_IN * HID];
    int tid = threadIdx.x;
    for (int i = tid; i < F_IN * HID; i += blockDim.x) sW[i] = W[i];
    __syncthreads();
    int t = blockIdx.x * blockDim.x + tid;
    if (t >= N_NODES * 32) return;
    int node = t >> 5, j = (t & 31) * 4;
    float xr[F_IN];
#pragma unroll
    for (int k = 0; k < F_IN; k++) xr[k] = x[node * F_IN + k];  // warp-broadcast
    float4 a = make_float4(0.f, 0.f, 0.f, 0.f);
#pragma unroll
    for (int k = 0; k < F_IN; k++) {
        const float* w = &sW[k * HID + j];
        a.x = fmaf(xr[k], w[0], a.x);
        a.y = fmaf(xr[k], w[1], a.y);
        a.z = fmaf(xr[k], w[2], a.z);
        a.w = fmaf(xr[k], w[3], a.w);
    }
    float dv = g_dinv[node];
    float s = dv * dv;
    ((float4*)h)[t] = a;
    ((float4*)init)[t] = make_float4(a.x * s, a.y * s, a.z * s, a.w * s);
}

// ---------------- edge scatter: agg[dst] += h[src] * dinv[src]*dinv[dst] ----------------
__global__ void k_scatter(const float* __restrict__ h, const int* __restrict__ ei,
                          float* __restrict__ agg) {
    int t = blockIdx.x * blockDim.x + threadIdx.x;
    int e = t >> 5;
    int lane = t & 31;
    if (e >= N_EDGES) return;
    int s = ei[e];
    int d = ei[N_EDGES + e];
    float norm = g_dinv[s] * g_dinv[d];
    float4 v = *(const float4*)(h + (size_t)s * HID + lane * 4);
    float* p = agg + (size_t)d * HID + lane * 4;
    asm volatile("red.global.add.v4.f32 [%0], {%1,%2,%3,%4};"
                 :: "l"(p), "f"(v.x * norm), "f"(v.y * norm), "f"(v.z * norm), "f"(v.w * norm)
                 : "memory");
}

// ---------------- bias + relu (elementwise, float4) ----------------
__global__ void k_bias_relu(const float4* __restrict__ in, const float* __restrict__ b,
                            float4* __restrict__ out) {
    int i = blockIdx.x * blockDim.x + threadIdx.x;
    if (i >= N_NODES * HID / 4) return;
    float4 bv = ((const float4*)b)[i & 31];
    float4 v = in[i];
    out[i] = make_float4(fmaxf(v.x + bv.x, 0.f), fmaxf(v.y + bv.y, 0.f),
                         fmaxf(v.z + bv.z, 0.f), fmaxf(v.w + bv.w, 0.f));
}

// ---------------- generic K=128 GEMM: C = A[M,128] @ B[128,N] (+bias) (+selfloop copy) --
template <int N, bool BIAS, bool SELF>
__global__ void gemm_k128(const float* __restrict__ A, const float* __restrict__ B,
                          const float* __restrict__ bias, float* __restrict__ C,
                          float* __restrict__ Cself) {
    constexpr int TK = 32;
    constexpr int MR = 32;
    constexpr int CG = N / 4;
    constexpr int RT = 256 / CG;
    constexpr int RPT = MR / RT;
    __shared__ float sA[MR][TK];
    __shared__ float sB[TK][N];
    const int tid = threadIdx.x;
    const int row0 = blockIdx.x * MR;
    const int cg = tid % CG;
    const int rt = tid / CG;

    float acc[RPT][4];
#pragma unroll
    for (int i = 0; i < RPT; i++)
#pragma unroll
        for (int j = 0; j < 4; j++) acc[i][j] = 0.f;

    for (int kt = 0; kt < 128; kt += TK) {
        {
            int r = tid >> 3, k4 = tid & 7;
            *(float4*)&sA[r][k4 * 4] =
                *(const float4*)&A[(size_t)(row0 + r) * 128 + kt + k4 * 4];
        }
        for (int i = tid; i < TK * N / 4; i += 256) {
            int k = i / (N / 4), j4 = i % (N / 4);
            *(float4*)&sB[k][j4 * 4] = *(const float4*)&B[(size_t)(kt + k) * N + j4 * 4];
        }
        __syncthreads();
#pragma unroll
        for (int k = 0; k < TK; k++) {
            float4 b = *(const float4*)&sB[k][cg * 4];
#pragma unroll
            for (int i = 0; i < RPT; i++) {
                float a = sA[rt * RPT + i][k];
                acc[i][0] = fmaf(a, b.x, acc[i][0]);
                acc[i][1] = fmaf(a, b.y, acc[i][1]);
                acc[i][2] = fmaf(a, b.z, acc[i][2]);
                acc[i][3] = fmaf(a, b.w, acc[i][3]);
            }
        }
        __syncthreads();
    }
    float4 bv = make_float4(0.f, 0.f, 0.f, 0.f);
    if (BIAS) bv = *(const float4*)&bias[cg * 4];
#pragma unroll
    for (int i = 0; i < RPT; i++) {
        int row = row0 + rt * RPT + i;
        float4 o = make_float4(acc[i][0] + bv.x, acc[i][1] + bv.y,
                               acc[i][2] + bv.z, acc[i][3] + bv.w);
        *(float4*)&C[(size_t)row * N + cg * 4] = o;
        if (SELF) {
            float dv = g_dinv[row];
            float s = dv * dv;
            *(float4*)&Cself[(size_t)row * N + cg * 4] =
                make_float4(o.x * s, o.y * s, o.z * s, o.w * s);
        }
    }
}

// ---------------- UV precompute: UV[n] = [ z[n]@Wd1_top + b1 | z[n]@Wd1_bot ] -----------
// A = z [100k,64]; logical B = [Wd1[0:64,:] | Wd1[64:128,:]]  -> [64, 256]
__global__ void k_uv(const float* __restrict__ Z, const float* __restrict__ Wd1,
                     const float* __restrict__ bd1, float* __restrict__ UV) {
    constexpr int TK = 32;
    constexpr int MR = 32;
    __shared__ float sA[MR][TK];
    __shared__ float sB[TK][256];
    const int tid = threadIdx.x;
    const int row0 = blockIdx.x * MR;
    const int cg = tid % 64;       // 64 col-groups of 4
    const int rt = tid / 64;       // 4 row groups, 8 rows each

    float acc[8][4];
#pragma unroll
    for (int i = 0; i < 8; i++)
#pragma unroll
        for (int j = 0; j < 4; j++) acc[i][j] = 0.f;

    for (int kt = 0; kt < 64; kt += TK) {
        {
            int r = tid >> 3, k4 = tid & 7;
            *(float4*)&sA[r][k4 * 4] =
                *(const float4*)&Z[(size_t)(row0 + r) * 64 + kt + k4 * 4];
        }
        for (int i = tid; i < TK * 64; i += 256) {  // TK*256/4 float4
            int k = i >> 6, j4 = i & 63;
            int j = j4 * 4;
            float4 v;
            if (j < 128) v = *(const float4*)&Wd1[(size_t)(kt + k) * 128 + j];
            else         v = *(const float4*)&Wd1[(size_t)(64 + kt + k) * 128 + (j - 128)];
            *(float4*)&sB[k][j] = v;
        }
        __syncthreads();
#pragma unroll
        for (int k = 0; k < TK; k++) {
            float4 b = *(const float4*)&sB[k][cg * 4];
#pragma unroll
            for (int i = 0; i < 8; i++) {
                float a = sA[rt * 8 + i][k];
                acc[i][0] = fmaf(a, b.x, acc[i][0]);
                acc[i][1] = fmaf(a, b.y, acc[i][1]);
                acc[i][2] = fmaf(a, b.z, acc[i][2]);
                acc[i][3] = fmaf(a, b.w, acc[i][3]);
            }
        }
        __syncthreads();
    }
    int col = cg * 4;
    float4 bv = (col < 128) ? *(const float4*)&bd1[col] : make_float4(0.f, 0.f, 0.f, 0.f);
#pragma unroll
    for (int i = 0; i < 8; i++) {
        int row = row0 + rt * 8 + i;
        *(float4*)&UV[(size_t)row * 256 + col] =
            make_float4(acc[i][0] + bv.x, acc[i][1] + bv.y, acc[i][2] + bv.z, acc[i][3] + bv.w);
    }
}

// ---------------- decoder: 128 queries/block; d1 via gather(U,V); stage2+3 in smem ------
// smem: s_d[128][128] (64KB) | s_w2[128][64] (32KB) | s_c2[128][64] (32KB) = 128KB
__global__ __launch_bounds__(256) void k_decoder(
    const float* __restrict__ uv, const int* __restrict__ qe,
    const float* __restrict__ Wd2, const float* __restrict__ bd2,
    const float* __restrict__ Wd3, const float* __restrict__ bd3,
    float* __restrict__ out) {
    extern __shared__ float smem[];
    float* s_d  = smem;                  // [128*128]
    float* s_w2 = smem + 16384;          // [128*64]
    float* s_c2 = smem + 16384 + 8192;   // [128*64]
    __shared__ int s_a[128], s_b[128];
    __shared__ float s_b2[EMB], s_w3[EMB];

    const int tid = threadIdx.x;
    const int q0 = blockIdx.x * 128;

    for (int i = tid; i < HID * EMB / 4; i += 256)
        ((float4*)s_w2)[i] = ((const float4*)Wd2)[i];
    if (tid < EMB) { s_b2[tid] = bd2[tid]; s_w3[tid] = Wd3[tid]; }
    if (tid < 128) {
        int qi = q0 + tid;
        s_a[tid] = qi < N_QUERY ? qe[qi] : 0;
        s_b[tid] = qi < N_QUERY ? qe[N_QUERY + qi] : 0;
    }
    __syncthreads();

    // stage 1: s_d[q] = relu(U'[a_q] + V[b_q])  (one warp per query row pass)
    const float4* uv4 = (const float4*)uv;
    for (int i = tid; i < 128 * 32; i += 256) {
        int q = i >> 5, c = i & 31;
        float4 u = uv4[(size_t)s_a[q] * 64 + c];
        float4 v = uv4[(size_t)s_b[q] * 64 + 32 + c];
        ((float4*)s_d)[q * 32 + c] =
            make_float4(fmaxf(u.x + v.x, 0.f), fmaxf(u.y + v.y, 0.f),
                        fmaxf(u.z + v.z, 0.f), fmaxf(u.w + v.w, 0.f));
    }
    __syncthreads();

    // stage 2: C2 = relu(s_d @ Wd2 + b2)  [128x64]; 8 rows x 4 cols per thread
    {
        const int cg = tid & 15, rt = tid >> 4;
        float acc[8][4];
#pragma unroll
        for (int i = 0; i < 8; i++)
#pragma unroll
            for (int j = 0; j < 4; j++) acc[i][j] = 0.f;
#pragma unroll 4
        for (int k = 0; k < HID; k++) {
            float4 b = *(const float4*)&s_w2[k * EMB + cg * 4];
#pragma unroll
            for (int i = 0; i < 8; i++) {
                float a = s_d[(rt * 8 + i) * HID + k];
                acc[i][0] = fmaf(a, b.x, acc[i][0]);
                acc[i][1] = fmaf(a, b.y, acc[i][1]);
                acc[i][2] = fmaf(a, b.z, acc[i][2]);
                acc[i][3] = fmaf(a, b.w, acc[i][3]);
            }
        }
        float4 bb = *(const float4*)&s_b2[cg * 4];
#pragma unroll
        for (int i = 0; i < 8; i++) {
            int row = rt * 8 + i;
            *(float4*)&s_c2[row * EMB + cg * 4] =
                make_float4(fmaxf(acc[i][0] + bb.x, 0.f), fmaxf(acc[i][1] + bb.y, 0.f),
                            fmaxf(acc[i][2] + bb.z, 0.f), fmaxf(acc[i][3] + bb.w, 0.f));
        }
    }
    __syncthreads();

    // stage 3: warp-collective dot + sigmoid (conflict-free: lane indexes banks)
    {
        const int wid = tid >> 5, lane = tid & 31;
        float b3 = bd3[0];
        for (int q = wid; q < 128; q += 8) {
            float s = s_c2[q * EMB + lane] * s_w3[lane]
                    + s_c2[q * EMB + 32 + lane] * s_w3[32 + lane];
#pragma unroll
            for (int off = 16; off > 0; off >>= 1) s += __shfl_xor_sync(0xffffffffu, s, off);
            int qi = q0 + q;
            if (lane == 0 && qi < N_QUERY) out[qi] = 1.0f / (1.0f + expf(-(s + b3)));
        }
    }
}

// ---------------- launch ----------------
extern "C" void kernel_launch(void* const* d_in, const int* in_sizes, int n_in,
                              void* d_out, int out_size) {
    const float* x   = (const float*)d_in[0];
    const int* ei    = (const int*)d_in[1];
    const int* qe    = (const int*)d_in[2];
    const float* W1  = (const float*)d_in[3];
    const float* b1  = (const float*)d_in[4];
    const float* W2  = (const float*)d_in[5];
    const float* b2  = (const float*)d_in[6];
    const float* Wfc = (const float*)d_in[7];
    const float* bfc = (const float*)d_in[8];
    const float* Wd1 = (const float*)d_in[9];
    const float* bd1 = (const float*)d_in[10];
    const float* Wd2 = (const float*)d_in[11];
    const float* bd2 = (const float*)d_in[12];
    const float* Wd3 = (const float*)d_in[13];
    const float* bd3 = (const float*)d_in[14];
    float* out = (float*)d_out;

    float *pA, *pB, *pC, *pZ, *pUV;
    { void* p; cudaGetSymbolAddress(&p, g_bufA); pA = (float*)p; }
    { void* p; cudaGetSymbolAddress(&p, g_bufB); pB = (float*)p; }
    { void* p; cudaGetSymbolAddress(&p, g_bufC); pC = (float*)p; }
    { void* p; cudaGetSymbolAddress(&p, g_z);    pZ = (float*)p; }
    { void* p; cudaGetSymbolAddress(&p, g_uv);   pUV = (float*)p; }

    cudaFuncSetAttribute(k_decoder, cudaFuncAttributeMaxDynamicSharedMemorySize, 131072);

    const int EV = N_NODES * HID / 4;

    k_deg_init<<<(N_NODES + 255) / 256, 256>>>();
    k_deg_count<<<(N_EDGES + 255) / 256, 256>>>(ei);
    k_dinv<<<(N_NODES + 255) / 256, 256>>>();

    // layer 1: h1 -> pA, agg-init -> pB (fused selfloop)
    k_mm_in<<<(N_NODES * 32 + 255) / 256, 256>>>(x, W1, pA, pB);
    k_scatter<<<(N_EDGES * 32) / 256, 256>>>(pA, ei, pB);
    k_bias_relu<<<(EV + 255) / 256, 256>>>((const float4*)pB, b1, (float4*)pA);

    // layer 2: h2 -> pB, agg-init -> pC (fused selfloop)
    gemm_k128<HID, false, true><<<N_NODES / 32, 256>>>(pA, W2, nullptr, pB, pC);
    k_scatter<<<(N_EDGES * 32) / 256, 256>>>(pB, ei, pC);
    k_bias_relu<<<(EV + 255) / 256, 256>>>((const float4*)pC, b2, (float4*)pB);

    // encoder fc: z -> pZ
    gemm_k128<EMB, true, false><<<N_NODES / 32, 256>>>(pB, Wfc, bfc, pZ, nullptr);

    // decoder stage-1 hoist: UV[n] = [z@Wd1_top + b1 | z@Wd1_bot]
    k_uv<<<N_NODES / 32, 256>>>(pZ, Wd1, bd1, pUV);

    // decoder: gather+relu, stage2 GEMM, stage3 dot
    k_decoder<<<(N_QUERY + 127) / 128, 256, 131072>>>(pUV, qe, Wd2, bd2, Wd3, bd3, out);
}

// round 4
// speedup vs baseline: 1.5307x; 1.1157x over previous
#include <cuda_runtime.h>
#include <math.h>

#define N_NODES 100000
#define N_EDGES 1600000
#define N_QUERY 500000
#define F_IN 7
#define HID 128
#define EMB 64

// ---------------- scratch (device globals) ----------------
__device__ float g_dinv[N_NODES];
__device__ int   g_cnt[N_NODES];
__device__ int   g_off[N_NODES + 1];
__device__ int   g_cur[N_NODES];
__device__ int   g_srcn[N_EDGES];
__device__ float g_nrm[N_EDGES];
__device__ float g_bufA[N_NODES * HID];
__device__ float g_bufB[N_NODES * HID];
__device__ float g_bufC[N_NODES * HID];
__device__ float g_z[N_NODES * EMB];
__device__ float g_uv[(size_t)N_NODES * 256];   // [U(128)+b1 | V(128)] per node

// ---------------- CSR build ----------------
__global__ void k_cnt_zero() {
    int i = blockIdx.x * blockDim.x + threadIdx.x;
    if (i < N_NODES) g_cnt[i] = 0;
}

__global__ void k_cnt(const int* __restrict__ ei) {
    int e = blockIdx.x * blockDim.x + threadIdx.x;
    if (e < N_EDGES) atomicAdd(&g_cnt[ei[N_EDGES + e]], 1);
}

// single-block exclusive scan of g_cnt -> g_off/g_cur; also writes g_off[N]
__global__ __launch_bounds__(1024) void k_scan() {
    __shared__ int ssum[1024];
    const int tid = threadIdx.x;
    const int CHUNK = (N_NODES + 1023) / 1024;
    int lo = tid * CHUNK;
    int hi = min(lo + CHUNK, N_NODES);
    int sum = 0;
    for (int i = lo; i < hi; i++) sum += g_cnt[i];
    ssum[tid] = sum;
    __syncthreads();
    for (int off = 1; off < 1024; off <<= 1) {
        int t = (tid >= off) ? ssum[tid - off] : 0;
        __syncthreads();
        if (tid >= off) ssum[tid] += t;
        __syncthreads();
    }
    int run = ssum[tid] - sum;  // exclusive prefix
    for (int i = lo; i < hi; i++) {
        g_off[i] = run;
        g_cur[i] = run;
        run += g_cnt[i];
    }
    if (lo < N_NODES && hi == N_NODES) g_off[N_NODES] = run;
}

__global__ void k_dinv() {
    int i = blockIdx.x * blockDim.x + threadIdx.x;
    if (i < N_NODES) g_dinv[i] = rsqrtf((float)g_cnt[i] + 1.0f);  // +1 self loop
}

__global__ void k_fill(const int* __restrict__ ei) {
    int e = blockIdx.x * blockDim.x + threadIdx.x;
    if (e >= N_EDGES) return;
    int s = ei[e];
    int d = ei[N_EDGES + e];
    int pos = atomicAdd(&g_cur[d], 1);
    g_srcn[pos] = s;
    g_nrm[pos] = g_dinv[s] * g_dinv[d];
}

// ---------------- layer-1 input matmul: h = x @ W1 ----------------
__global__ void k_mm_in(const float* __restrict__ x, const float* __restrict__ W,
                        float* __restrict__ h) {
    __shared__ float sW[F_IN * HID];
    int tid = threadIdx.x;
    for (int i = tid; i < F_IN * HID; i += blockDim.x) sW[i] = W[i];
    __syncthreads();
    int t = blockIdx.x * blockDim.x + tid;
    if (t >= N_NODES * 32) return;
    int node = t >> 5, j = (t & 31) * 4;
    float xr[F_IN];
#pragma unroll
    for (int k = 0; k < F_IN; k++) xr[k] = x[node * F_IN + k];  // warp-broadcast
    float4 a = make_float4(0.f, 0.f, 0.f, 0.f);
#pragma unroll
    for (int k = 0; k < F_IN; k++) {
        const float* w = &sW[k * HID + j];
        a.x = fmaf(xr[k], w[0], a.x);
        a.y = fmaf(xr[k], w[1], a.y);
        a.z = fmaf(xr[k], w[2], a.z);
        a.w = fmaf(xr[k], w[3], a.w);
    }
    ((float4*)h)[t] = a;
}

// ---------------- fused CSR aggregation: out = relu(selfloop + sum_in + bias) ----------
// One warp per node; lane = float4 column chunk; 4-way edge unroll for MLP.
__global__ __launch_bounds__(256) void k_agg(const float* __restrict__ h,
                                             const float* __restrict__ bias,
                                             float* __restrict__ out) {
    int t = blockIdx.x * blockDim.x + threadIdx.x;
    int node = t >> 5, lane = t & 31;
    if (node >= N_NODES) return;
    const float4* h4 = (const float4*)h;
    float dv = g_dinv[node];
    float sl = dv * dv;
    float4 a = h4[(size_t)node * 32 + lane];
    float4 acc = make_float4(a.x * sl, a.y * sl, a.z * sl, a.w * sl);
    int e = g_off[node];
    const int end = g_off[node + 1];
    for (; e + 4 <= end; e += 4) {
        int s0 = g_srcn[e], s1 = g_srcn[e + 1], s2 = g_srcn[e + 2], s3 = g_srcn[e + 3];
        float n0 = g_nrm[e], n1 = g_nrm[e + 1], n2 = g_nrm[e + 2], n3 = g_nrm[e + 3];
        float4 v0 = h4[(size_t)s0 * 32 + lane];
        float4 v1 = h4[(size_t)s1 * 32 + lane];
        float4 v2 = h4[(size_t)s2 * 32 + lane];
        float4 v3 = h4[(size_t)s3 * 32 + lane];
        acc.x = fmaf(v0.x, n0, fmaf(v1.x, n1, fmaf(v2.x, n2, fmaf(v3.x, n3, acc.x))));
        acc.y = fmaf(v0.y, n0, fmaf(v1.y, n1, fmaf(v2.y, n2, fmaf(v3.y, n3, acc.y))));
        acc.z = fmaf(v0.z, n0, fmaf(v1.z, n1, fmaf(v2.z, n2, fmaf(v3.z, n3, acc.z))));
        acc.w = fmaf(v0.w, n0, fmaf(v1.w, n1, fmaf(v2.w, n2, fmaf(v3.w, n3, acc.w))));
    }
    for (; e < end; e++) {
        int s0 = g_srcn[e];
        float n0 = g_nrm[e];
        float4 v0 = h4[(size_t)s0 * 32 + lane];
        acc.x = fmaf(v0.x, n0, acc.x);
        acc.y = fmaf(v0.y, n0, acc.y);
        acc.z = fmaf(v0.z, n0, acc.z);
        acc.w = fmaf(v0.w, n0, acc.w);
    }
    float4 bv = ((const float4*)bias)[lane];
    ((float4*)out)[(size_t)node * 32 + lane] =
        make_float4(fmaxf(acc.x + bv.x, 0.f), fmaxf(acc.y + bv.y, 0.f),
                    fmaxf(acc.z + bv.z, 0.f), fmaxf(acc.w + bv.w, 0.f));
}

// ---------------- generic K=128 GEMM: C = A[M,128] @ B[128,N] (+bias) ----------------
template <int N, bool BIAS>
__global__ void gemm_k128(const float* __restrict__ A, const float* __restrict__ B,
                          const float* __restrict__ bias, float* __restrict__ C) {
    constexpr int TK = 32;
    constexpr int MR = 32;
    constexpr int CG = N / 4;
    constexpr int RT = 256 / CG;
    constexpr int RPT = MR / RT;
    __shared__ float sA[MR][TK];
    __shared__ float sB[TK][N];
    const int tid = threadIdx.x;
    const int row0 = blockIdx.x * MR;
    const int cg = tid % CG;
    const int rt = tid / CG;

    float acc[RPT][4];
#pragma unroll
    for (int i = 0; i < RPT; i++)
#pragma unroll
        for (int j = 0; j < 4; j++) acc[i][j] = 0.f;

    for (int kt = 0; kt < 128; kt += TK) {
        {
            int r = tid >> 3, k4 = tid & 7;
            *(float4*)&sA[r][k4 * 4] =
                *(const float4*)&A[(size_t)(row0 + r) * 128 + kt + k4 * 4];
        }
        for (int i = tid; i < TK * N / 4; i += 256) {
            int k = i / (N / 4), j4 = i % (N / 4);
            *(float4*)&sB[k][j4 * 4] = *(const float4*)&B[(size_t)(kt + k) * N + j4 * 4];
        }
        __syncthreads();
#pragma unroll
        for (int k = 0; k < TK; k++) {
            float4 b = *(const float4*)&sB[k][cg * 4];
#pragma unroll
            for (int i = 0; i < RPT; i++) {
                float a = sA[rt * RPT + i][k];
                acc[i][0] = fmaf(a, b.x, acc[i][0]);
                acc[i][1] = fmaf(a, b.y, acc[i][1]);
                acc[i][2] = fmaf(a, b.z, acc[i][2]);
                acc[i][3] = fmaf(a, b.w, acc[i][3]);
            }
        }
        __syncthreads();
    }
    float4 bv = make_float4(0.f, 0.f, 0.f, 0.f);
    if (BIAS) bv = *(const float4*)&bias[cg * 4];
#pragma unroll
    for (int i = 0; i < RPT; i++) {
        int row = row0 + rt * RPT + i;
        *(float4*)&C[(size_t)row * N + cg * 4] =
            make_float4(acc[i][0] + bv.x, acc[i][1] + bv.y, acc[i][2] + bv.z, acc[i][3] + bv.w);
    }
}

// ---------------- UV precompute: UV[n] = [ z[n]@Wd1_top + b1 | z[n]@Wd1_bot ] -----------
__global__ void k_uv(const float* __restrict__ Z, const float* __restrict__ Wd1,
                     const float* __restrict__ bd1, float* __restrict__ UV) {
    constexpr int TK = 32;
    constexpr int MR = 32;
    __shared__ float sA[MR][TK];
    __shared__ float sB[TK][256];
    const int tid = threadIdx.x;
    const int row0 = blockIdx.x * MR;
    const int cg = tid % 64;
    const int rt = tid / 64;

    float acc[8][4];
#pragma unroll
    for (int i = 0; i < 8; i++)
#pragma unroll
        for (int j = 0; j < 4; j++) acc[i][j] = 0.f;

    for (int kt = 0; kt < 64; kt += TK) {
        {
            int r = tid >> 3, k4 = tid & 7;
            *(float4*)&sA[r][k4 * 4] =
                *(const float4*)&Z[(size_t)(row0 + r) * 64 + kt + k4 * 4];
        }
        for (int i = tid; i < TK * 64; i += 256) {
            int k = i >> 6, j4 = i & 63;
            int j = j4 * 4;
            float4 v;
            if (j < 128) v = *(const float4*)&Wd1[(size_t)(kt + k) * 128 + j];
            else         v = *(const float4*)&Wd1[(size_t)(64 + kt + k) * 128 + (j - 128)];
            *(float4*)&sB[k][j] = v;
        }
        __syncthreads();
#pragma unroll
        for (int k = 0; k < TK; k++) {
            float4 b = *(const float4*)&sB[k][cg * 4];
#pragma unroll
            for (int i = 0; i < 8; i++) {
                float a = sA[rt * 8 + i][k];
                acc[i][0] = fmaf(a, b.x, acc[i][0]);
                acc[i][1] = fmaf(a, b.y, acc[i][1]);
                acc[i][2] = fmaf(a, b.z, acc[i][2]);
                acc[i][3] = fmaf(a, b.w, acc[i][3]);
            }
        }
        __syncthreads();
    }
    int col = cg * 4;
    float4 bv = (col < 128) ? *(const float4*)&bd1[col] : make_float4(0.f, 0.f, 0.f, 0.f);
#pragma unroll
    for (int i = 0; i < 8; i++) {
        int row = row0 + rt * 8 + i;
        *(float4*)&UV[(size_t)row * 256 + col] =
            make_float4(acc[i][0] + bv.x, acc[i][1] + bv.y, acc[i][2] + bv.z, acc[i][3] + bv.w);
    }
}

// ---------------- decoder: 128 queries/block; d1 via gather(U,V); stage2+3 in smem ------
__global__ __launch_bounds__(256) void k_decoder(
    const float* __restrict__ uv, const int* __restrict__ qe,
    const float* __restrict__ Wd2, const float* __restrict__ bd2,
    const float* __restrict__ Wd3, const float* __restrict__ bd3,
    float* __restrict__ out) {
    extern __shared__ float smem[];
    float* s_d  = smem;                  // [128*128]
    float* s_w2 = smem + 16384;          // [128*64]
    float* s_c2 = smem + 16384 + 8192;   // [128*64]
    __shared__ int s_a[128], s_b[128];
    __shared__ float s_b2[EMB], s_w3[EMB];

    const int tid = threadIdx.x;
    const int q0 = blockIdx.x * 128;

    for (int i = tid; i < HID * EMB / 4; i += 256)
        ((float4*)s_w2)[i] = ((const float4*)Wd2)[i];
    if (tid < EMB) { s_b2[tid] = bd2[tid]; s_w3[tid] = Wd3[tid]; }
    if (tid < 128) {
        int qi = q0 + tid;
        s_a[tid] = qi < N_QUERY ? qe[qi] : 0;
        s_b[tid] = qi < N_QUERY ? qe[N_QUERY + qi] : 0;
    }
    __syncthreads();

    // stage 1: s_d[q] = relu(U[a_q] + V[b_q])
    const float4* uv4 = (const float4*)uv;
    for (int i = tid; i < 128 * 32; i += 256) {
        int q = i >> 5, c = i & 31;
        float4 u = uv4[(size_t)s_a[q] * 64 + c];
        float4 v = uv4[(size_t)s_b[q] * 64 + 32 + c];
        ((float4*)s_d)[q * 32 + c] =
            make_float4(fmaxf(u.x + v.x, 0.f), fmaxf(u.y + v.y, 0.f),
                        fmaxf(u.z + v.z, 0.f), fmaxf(u.w + v.w, 0.f));
    }
    __syncthreads();

    // stage 2: C2 = relu(s_d @ Wd2 + b2)  [128x64]; 8 rows x 4 cols per thread
    {
        const int cg = tid & 15, rt = tid >> 4;
        float acc[8][4];
#pragma unroll
        for (int i = 0; i < 8; i++)
#pragma unroll
            for (int j = 0; j < 4; j++) acc[i][j] = 0.f;
#pragma unroll 4
        for (int k = 0; k < HID; k++) {
            float4 b = *(const float4*)&s_w2[k * EMB + cg * 4];
#pragma unroll
            for (int i = 0; i < 8; i++) {
                float a = s_d[(rt * 8 + i) * HID + k];
                acc[i][0] = fmaf(a, b.x, acc[i][0]);
                acc[i][1] = fmaf(a, b.y, acc[i][1]);
                acc[i][2] = fmaf(a, b.z, acc[i][2]);
                acc[i][3] = fmaf(a, b.w, acc[i][3]);
            }
        }
        float4 bb = *(const float4*)&s_b2[cg * 4];
#pragma unroll
        for (int i = 0; i < 8; i++) {
            int row = rt * 8 + i;
            *(float4*)&s_c2[row * EMB + cg * 4] =
                make_float4(fmaxf(acc[i][0] + bb.x, 0.f), fmaxf(acc[i][1] + bb.y, 0.f),
                            fmaxf(acc[i][2] + bb.z, 0.f), fmaxf(acc[i][3] + bb.w, 0.f));
        }
    }
    __syncthreads();

    // stage 3: warp-collective dot + sigmoid
    {
        const int wid = tid >> 5, lane = tid & 31;
        float b3 = bd3[0];
        for (int q = wid; q < 128; q += 8) {
            float s = s_c2[q * EMB + lane] * s_w3[lane]
                    + s_c2[q * EMB + 32 + lane] * s_w3[32 + lane];
#pragma unroll
            for (int off = 16; off > 0; off >>= 1) s += __shfl_xor_sync(0xffffffffu, s, off);
            int qi = q0 + q;
            if (lane == 0 && qi < N_QUERY) out[qi] = 1.0f / (1.0f + expf(-(s + b3)));
        }
    }
}

// ---------------- launch ----------------
extern "C" void kernel_launch(void* const* d_in, const int* in_sizes, int n_in,
                              void* d_out, int out_size) {
    const float* x   = (const float*)d_in[0];
    const int* ei    = (const int*)d_in[1];
    const int* qe    = (const int*)d_in[2];
    const float* W1  = (const float*)d_in[3];
    const float* b1  = (const float*)d_in[4];
    const float* W2  = (const float*)d_in[5];
    const float* b2  = (const float*)d_in[6];
    const float* Wfc = (const float*)d_in[7];
    const float* bfc = (const float*)d_in[8];
    const float* Wd1 = (const float*)d_in[9];
    const float* bd1 = (const float*)d_in[10];
    const float* Wd2 = (const float*)d_in[11];
    const float* bd2 = (const float*)d_in[12];
    const float* Wd3 = (const float*)d_in[13];
    const float* bd3 = (const float*)d_in[14];
    float* out = (float*)d_out;

    float *pA, *pB, *pC, *pZ, *pUV;
    { void* p; cudaGetSymbolAddress(&p, g_bufA); pA = (float*)p; }
    { void* p; cudaGetSymbolAddress(&p, g_bufB); pB = (float*)p; }
    { void* p; cudaGetSymbolAddress(&p, g_bufC); pC = (float*)p; }
    { void* p; cudaGetSymbolAddress(&p, g_z);    pZ = (float*)p; }
    { void* p; cudaGetSymbolAddress(&p, g_uv);   pUV = (float*)p; }

    cudaFuncSetAttribute(k_decoder, cudaFuncAttributeMaxDynamicSharedMemorySize, 131072);

    // CSR build
    k_cnt_zero<<<(N_NODES + 255) / 256, 256>>>();
    k_cnt<<<(N_EDGES + 255) / 256, 256>>>(ei);
    k_scan<<<1, 1024>>>();
    k_dinv<<<(N_NODES + 255) / 256, 256>>>();
    k_fill<<<(N_EDGES + 255) / 256, 256>>>(ei);

    // layer 1: h1 -> pA; agg+bias+relu -> pB
    k_mm_in<<<(N_NODES * 32 + 255) / 256, 256>>>(x, W1, pA);
    k_agg<<<(N_NODES * 32 + 255) / 256, 256>>>(pA, b1, pB);

    // layer 2: h2 = pB@W2 -> pC; agg+bias+relu -> pA
    gemm_k128<HID, false><<<N_NODES / 32, 256>>>(pB, W2, nullptr, pC);
    k_agg<<<(N_NODES * 32 + 255) / 256, 256>>>(pC, b2, pA);

    // encoder fc: z -> pZ
    gemm_k128<EMB, true><<<N_NODES / 32, 256>>>(pA, Wfc, bfc, pZ);

    // decoder stage-1 hoist + decoder
    k_uv<<<N_NODES / 32, 256>>>(pZ, Wd1, bd1, pUV);
    k_decoder<<<(N_QUERY + 127) / 128, 256, 131072>>>(pUV, qe, Wd2, bd2, Wd3, bd3, out);
}

// round 5
// speedup vs baseline: 1.5851x; 1.0356x over previous
#include <cuda_runtime.h>
#include <math.h>

#define N_NODES 100000
#define N_EDGES 1600000
#define N_QUERY 500000
#define F_IN 7
#define HID 128
#define EMB 64

// ---------------- scratch (device globals) ----------------
__device__ float g_dinv[N_NODES];
__device__ int   g_cnt[N_NODES];
__device__ int   g_off[N_NODES + 1];
__device__ int   g_cur[N_NODES];
__device__ int   g_srcn[N_EDGES];
__device__ float g_bufA[N_NODES * HID];
__device__ float g_bufB[N_NODES * HID];
__device__ float g_bufC[N_NODES * HID];
__device__ float g_z[N_NODES * EMB];
__device__ float g_uv[(size_t)N_NODES * 256];   // [U(128)+b1 | V(128)] per node
__device__ float g_wd1p[64 * 256];              // packed [Wd1_top | Wd1_bot]
__device__ float g_bc[256];                     // [bd1 | 0]

// ---------------- CSR build ----------------
__global__ void k_cnt_zero() {
    int i = blockIdx.x * blockDim.x + threadIdx.x;
    if (i < N_NODES) g_cnt[i] = 0;
}

__global__ void k_cnt(const int* __restrict__ ei) {
    int e = blockIdx.x * blockDim.x + threadIdx.x;
    if (e < N_EDGES) atomicAdd(&g_cnt[ei[N_EDGES + e]], 1);
}

__global__ __launch_bounds__(1024) void k_scan() {
    __shared__ int ssum[1024];
    const int tid = threadIdx.x;
    const int CHUNK = (N_NODES + 1023) / 1024;
    int lo = tid * CHUNK;
    int hi = min(lo + CHUNK, N_NODES);
    int sum = 0;
    for (int i = lo; i < hi; i++) sum += g_cnt[i];
    ssum[tid] = sum;
    __syncthreads();
    for (int off = 1; off < 1024; off <<= 1) {
        int t = (tid >= off) ? ssum[tid - off] : 0;
        __syncthreads();
        if (tid >= off) ssum[tid] += t;
        __syncthreads();
    }
    int run = ssum[tid] - sum;
    for (int i = lo; i < hi; i++) {
        g_off[i] = run;
        g_cur[i] = run;
        run += g_cnt[i];
    }
    if (lo < N_NODES && hi == N_NODES) g_off[N_NODES] = run;
}

__global__ void k_dinv() {
    int i = blockIdx.x * blockDim.x + threadIdx.x;
    if (i < N_NODES) g_dinv[i] = rsqrtf((float)g_cnt[i] + 1.0f);
}

__global__ void k_fill(const int* __restrict__ ei) {
    int e = blockIdx.x * blockDim.x + threadIdx.x;
    if (e >= N_EDGES) return;
    int s = ei[e];
    int d = ei[N_EDGES + e];
    int pos = atomicAdd(&g_cur[d], 1);
    g_srcn[pos] = s;
}

// ---------------- pack decoder stage-1 weights ----------------
__global__ void k_pack(const float* __restrict__ Wd1, const float* __restrict__ bd1) {
    int idx = blockIdx.x * blockDim.x + threadIdx.x;
    if (idx < 64 * 256) {
        int k = idx >> 8, j = idx & 255;
        g_wd1p[idx] = (j < 128) ? Wd1[k * 128 + j] : Wd1[(64 + k) * 128 + (j - 128)];
    }
    if (idx < 256) g_bc[idx] = (idx < 128) ? bd1[idx] : 0.f;
}

// ---------------- layer-1 input matmul: hs1 = (x @ W1) * dinv ----------------
__global__ void k_mm_in(const float* __restrict__ x, const float* __restrict__ W,
                        float* __restrict__ hs) {
    __shared__ float sW[F_IN * HID];
    int tid = threadIdx.x;
    for (int i = tid; i < F_IN * HID; i += blockDim.x) sW[i] = W[i];
    __syncthreads();
    int t = blockIdx.x * blockDim.x + tid;
    if (t >= N_NODES * 32) return;
    int node = t >> 5, j = (t & 31) * 4;
    float xr[F_IN];
#pragma unroll
    for (int k = 0; k < F_IN; k++) xr[k] = x[node * F_IN + k];
    float4 a = make_float4(0.f, 0.f, 0.f, 0.f);
#pragma unroll
    for (int k = 0; k < F_IN; k++) {
        const float* w = &sW[k * HID + j];
        a.x = fmaf(xr[k], w[0], a.x);
        a.y = fmaf(xr[k], w[1], a.y);
        a.z = fmaf(xr[k], w[2], a.z);
        a.w = fmaf(xr[k], w[3], a.w);
    }
    float dv = g_dinv[node];
    ((float4*)hs)[t] = make_float4(a.x * dv, a.y * dv, a.z * dv, a.w * dv);
}

// ---------------- fused CSR aggregation: out = relu(dinv[d]*(sum hs[src] + hs[d]) + b) --
__global__ __launch_bounds__(256) void k_agg(const float* __restrict__ hs,
                                             const float* __restrict__ bias,
                                             float* __restrict__ out) {
    int t = blockIdx.x * blockDim.x + threadIdx.x;
    int node = t >> 5, lane = t & 31;
    if (node >= N_NODES) return;
    const float4* h4 = (const float4*)hs;
    float4 acc = h4[(size_t)node * 32 + lane];   // self (hs[d])
    int e = g_off[node];
    const int end = g_off[node + 1];
    for (; e + 4 <= end; e += 4) {
        int s0 = g_srcn[e], s1 = g_srcn[e + 1], s2 = g_srcn[e + 2], s3 = g_srcn[e + 3];
        float4 v0 = h4[(size_t)s0 * 32 + lane];
        float4 v1 = h4[(size_t)s1 * 32 + lane];
        float4 v2 = h4[(size_t)s2 * 32 + lane];
        float4 v3 = h4[(size_t)s3 * 32 + lane];
        acc.x += v0.x + v1.x + v2.x + v3.x;
        acc.y += v0.y + v1.y + v2.y + v3.y;
        acc.z += v0.z + v1.z + v2.z + v3.z;
        acc.w += v0.w + v1.w + v2.w + v3.w;
    }
    for (; e < end; e++) {
        float4 v0 = h4[(size_t)g_srcn[e] * 32 + lane];
        acc.x += v0.x; acc.y += v0.y; acc.z += v0.z; acc.w += v0.w;
    }
    float dv = g_dinv[node];
    float4 bv = ((const float4*)bias)[lane];
    ((float4*)out)[(size_t)node * 32 + lane] =
        make_float4(fmaxf(fmaf(acc.x, dv, bv.x), 0.f), fmaxf(fmaf(acc.y, dv, bv.y), 0.f),
                    fmaxf(fmaf(acc.z, dv, bv.z), 0.f), fmaxf(fmaf(acc.w, dv, bv.w), 0.f));
}

// ---------------- high-efficiency tiled GEMM: C[M,NT] = A[M,KD] @ B[KD,NT] -------------
// 256 threads, 8x8 register tile per thread (MT*NT = 16384), TK=16, A transposed in smem.
// EPI 0: C = acc * dinv[row];  EPI 1: C = acc + bias[col]
template <int MT, int NT, int KD, int EPI>
__global__ __launch_bounds__(256) void gemm_tiled(const float* __restrict__ A,
                                                  const float* __restrict__ B,
                                                  const float* __restrict__ bias,
                                                  float* __restrict__ C) {
    constexpr int TK = 16;
    constexpr int PITCH = MT + 4;
    __shared__ float sAT[TK][PITCH];
    __shared__ float sB[TK][NT];
    const int tid = threadIdx.x;
    const int row0 = blockIdx.x * MT;
    constexpr int NG = NT / 8;
    const int tx = tid % NG;
    const int ty = tid / NG;

    float acc[8][8];
#pragma unroll
    for (int i = 0; i < 8; i++)
#pragma unroll
        for (int j = 0; j < 8; j++) acc[i][j] = 0.f;

    for (int kt = 0; kt < KD; kt += TK) {
        // load A tile (MT x TK), store transposed
#pragma unroll
        for (int l = 0; l < MT * TK / 1024; l++) {
            int idx = tid + l * 256;
            int row = idx >> 2, kq = idx & 3;
            int grow = row0 + row;
            if (grow >= N_NODES) grow = N_NODES - 1;
            float4 v = *(const float4*)&A[(size_t)grow * KD + kt + kq * 4];
            sAT[kq * 4 + 0][row] = v.x;
            sAT[kq * 4 + 1][row] = v.y;
            sAT[kq * 4 + 2][row] = v.z;
            sAT[kq * 4 + 3][row] = v.w;
        }
        // load B tile (TK x NT)
#pragma unroll
        for (int l = 0; l < TK * NT / 1024; l++) {
            int idx = tid + l * 256;
            int kk = idx / (NT / 4), j4 = idx % (NT / 4);
            *(float4*)&sB[kk][j4 * 4] = *(const float4*)&B[(size_t)(kt + kk) * NT + j4 * 4];
        }
        __syncthreads();
#pragma unroll
        for (int k = 0; k < TK; k++) {
            float4 a0 = *(const float4*)&sAT[k][ty * 8];
            float4 a1 = *(const float4*)&sAT[k][ty * 8 + 4];
            float4 b0 = *(const float4*)&sB[k][tx * 8];
            float4 b1 = *(const float4*)&sB[k][tx * 8 + 4];
            float av[8] = {a0.x, a0.y, a0.z, a0.w, a1.x, a1.y, a1.z, a1.w};
            float bv[8] = {b0.x, b0.y, b0.z, b0.w, b1.x, b1.y, b1.z, b1.w};
#pragma unroll
            for (int i = 0; i < 8; i++)
#pragma unroll
                for (int j = 0; j < 8; j++) acc[i][j] = fmaf(av[i], bv[j], acc[i][j]);
        }
        __syncthreads();
    }

    float bv0[8];
    if (EPI == 1) {
#pragma unroll
        for (int j = 0; j < 8; j++) bv0[j] = bias[tx * 8 + j];
    }
#pragma unroll
    for (int i = 0; i < 8; i++) {
        int row = row0 + ty * 8 + i;
        if (row >= N_NODES) break;
        float r[8];
        if (EPI == 0) {
            float s = g_dinv[row];
#pragma unroll
            for (int j = 0; j < 8; j++) r[j] = acc[i][j] * s;
        } else {
#pragma unroll
            for (int j = 0; j < 8; j++) r[j] = acc[i][j] + bv0[j];
        }
        *(float4*)&C[(size_t)row * NT + tx * 8]     = make_float4(r[0], r[1], r[2], r[3]);
        *(float4*)&C[(size_t)row * NT + tx * 8 + 4] = make_float4(r[4], r[5], r[6], r[7]);
    }
}

// ---------------- decoder: 128 queries/block; transposed activation tile ----------------
// dyn smem (floats): s_dT[128][132] | s_w2[128*64] | s_c2T[64][132]  = 134144 bytes
__global__ __launch_bounds__(256) void k_decoder(
    const float* __restrict__ uv, const int* __restrict__ qe,
    const float* __restrict__ Wd2, const float* __restrict__ bd2,
    const float* __restrict__ Wd3, const float* __restrict__ bd3,
    float* __restrict__ out) {
    extern __shared__ float smem[];
    float* s_dT  = smem;                 // [128][132]  (k-major, pitch 132)
    float* s_w2  = smem + 16896;         // [128*64]
    float* s_c2T = smem + 25088;         // [64][132]
    __shared__ int s_a[128], s_b[128];
    __shared__ float s_b2[EMB], s_w3[EMB];

    const int tid = threadIdx.x;
    const int q0 = blockIdx.x * 128;

    for (int i = tid; i < HID * EMB / 4; i += 256)
        ((float4*)s_w2)[i] = ((const float4*)Wd2)[i];
    if (tid < EMB) { s_b2[tid] = bd2[tid]; s_w3[tid] = Wd3[tid]; }
    if (tid < 128) {
        int qi = q0 + tid;
        s_a[tid] = qi < N_QUERY ? qe[qi] : 0;
        s_b[tid] = qi < N_QUERY ? qe[N_QUERY + qi] : 0;
    }
    __syncthreads();

    // stage 1: s_dT[c][q] = relu(U[a_q][c] + V[b_q][c])
    const float4* uv4 = (const float4*)uv;
    for (int i = tid; i < 128 * 32; i += 256) {
        int q = i & 127, c4 = i >> 7;
        float4 u = uv4[(size_t)s_a[q] * 64 + c4];
        float4 v = uv4[(size_t)s_b[q] * 64 + 32 + c4];
        int base = (c4 * 4) * 132 + q;
        s_dT[base]           = fmaxf(u.x + v.x, 0.f);
        s_dT[base + 132]     = fmaxf(u.y + v.y, 0.f);
        s_dT[base + 2 * 132] = fmaxf(u.z + v.z, 0.f);
        s_dT[base + 3 * 132] = fmaxf(u.w + v.w, 0.f);
    }
    __syncthreads();

    // stage 2: c2T[c][q] = relu(sum_k dT[k][q] * w2[k][c] + b2[c]); 8q x 4c per thread
    {
        const int tx = tid & 15, ty = tid >> 4;
        const int qb = tx * 8, cb = ty * 4;
        float acc[8][4];
#pragma unroll
        for (int i = 0; i < 8; i++)
#pragma unroll
            for (int j = 0; j < 4; j++) acc[i][j] = 0.f;
#pragma unroll 4
        for (int k = 0; k < HID; k++) {
            float4 a0 = *(const float4*)&s_dT[k * 132 + qb];
            float4 a1 = *(const float4*)&s_dT[k * 132 + qb + 4];
            float4 b  = *(const float4*)&s_w2[k * EMB + cb];
            float av[8] = {a0.x, a0.y, a0.z, a0.w, a1.x, a1.y, a1.z, a1.w};
#pragma unroll
            for (int i = 0; i < 8; i++) {
                acc[i][0] = fmaf(av[i], b.x, acc[i][0]);
                acc[i][1] = fmaf(av[i], b.y, acc[i][1]);
                acc[i][2] = fmaf(av[i], b.z, acc[i][2]);
                acc[i][3] = fmaf(av[i], b.w, acc[i][3]);
            }
        }
#pragma unroll
        for (int j = 0; j < 4; j++) {
            float bb = s_b2[cb + j];
            float4 lo = make_float4(fmaxf(acc[0][j] + bb, 0.f), fmaxf(acc[1][j] + bb, 0.f),
                                    fmaxf(acc[2][j] + bb, 0.f), fmaxf(acc[3][j] + bb, 0.f));
            float4 hi = make_float4(fmaxf(acc[4][j] + bb, 0.f), fmaxf(acc[5][j] + bb, 0.f),
                                    fmaxf(acc[6][j] + bb, 0.f), fmaxf(acc[7][j] + bb, 0.f));
            *(float4*)&s_c2T[(cb + j) * 132 + qb]     = lo;
            *(float4*)&s_c2T[(cb + j) * 132 + qb + 4] = hi;
        }
    }
    __syncthreads();

    // stage 3: logits + sigmoid (dense, conflict-free along q)
    if (tid < 128) {
        int qi = q0 + tid;
        if (qi < N_QUERY) {
            float s = bd3[0];
#pragma unroll 8
            for (int c = 0; c < EMB; c++) s = fmaf(s_c2T[c * 132 + tid], s_w3[c], s);
            out[qi] = 1.0f / (1.0f + expf(-s));
        }
    }
}

// ---------------- launch ----------------
extern "C" void kernel_launch(void* const* d_in, const int* in_sizes, int n_in,
                              void* d_out, int out_size) {
    const float* x   = (const float*)d_in[0];
    const int* ei    = (const int*)d_in[1];
    const int* qe    = (const int*)d_in[2];
    const float* W1  = (const float*)d_in[3];
    const float* b1  = (const float*)d_in[4];
    const float* W2  = (const float*)d_in[5];
    const float* b2  = (const float*)d_in[6];
    const float* Wfc = (const float*)d_in[7];
    const float* bfc = (const float*)d_in[8];
    const float* Wd1 = (const float*)d_in[9];
    const float* bd1 = (const float*)d_in[10];
    const float* Wd2 = (const float*)d_in[11];
    const float* bd2 = (const float*)d_in[12];
    const float* Wd3 = (const float*)d_in[13];
    const float* bd3 = (const float*)d_in[14];
    float* out = (float*)d_out;

    float *pA, *pB, *pC, *pZ, *pUV, *pW1P, *pBC;
    { void* p; cudaGetSymbolAddress(&p, g_bufA); pA = (float*)p; }
    { void* p; cudaGetSymbolAddress(&p, g_bufB); pB = (float*)p; }
    { void* p; cudaGetSymbolAddress(&p, g_bufC); pC = (float*)p; }
    { void* p; cudaGetSymbolAddress(&p, g_z);    pZ = (float*)p; }
    { void* p; cudaGetSymbolAddress(&p, g_uv);   pUV = (float*)p; }
    { void* p; cudaGetSymbolAddress(&p, g_wd1p); pW1P = (float*)p; }
    { void* p; cudaGetSymbolAddress(&p, g_bc);   pBC = (float*)p; }

    cudaFuncSetAttribute(k_decoder, cudaFuncAttributeMaxDynamicSharedMemorySize, 134144);

    // CSR build + weight packing
    k_cnt_zero<<<(N_NODES + 255) / 256, 256>>>();
    k_cnt<<<(N_EDGES + 255) / 256, 256>>>(ei);
    k_scan<<<1, 1024>>>();
    k_dinv<<<(N_NODES + 255) / 256, 256>>>();
    k_fill<<<(N_EDGES + 255) / 256, 256>>>(ei);
    k_pack<<<64, 256>>>(Wd1, bd1);

    // layer 1: hs1 -> pA; agg -> pB (h1')
    k_mm_in<<<(N_NODES * 32 + 255) / 256, 256>>>(x, W1, pA);
    k_agg<<<(N_NODES * 32 + 255) / 256, 256>>>(pA, b1, pB);

    // layer 2: hs2 = (pB@W2)*dinv -> pC; agg -> pA (h2')
    gemm_tiled<128, 128, 128, 0><<<(N_NODES + 127) / 128, 256>>>(pB, W2, nullptr, pC);
    k_agg<<<(N_NODES * 32 + 255) / 256, 256>>>(pC, b2, pA);

    // encoder fc: z = pA@Wfc + bfc -> pZ
    gemm_tiled<256, 64, 128, 1><<<(N_NODES + 255) / 256, 256>>>(pA, Wfc, bfc, pZ);

    // decoder stage-1 hoist: UV = z @ [Wd1_top|Wd1_bot] + [bd1|0]
    gemm_tiled<64, 256, 64, 1><<<(N_NODES + 63) / 64, 256>>>(pZ, pW1P, pBC, pUV);

    // decoder
    k_decoder<<<(N_QUERY + 127) / 128, 256, 134144>>>(pUV, qe, Wd2, bd2, Wd3, bd3, out);
}

// round 6
// speedup vs baseline: 1.8766x; 1.1839x over previous
#include <cuda_runtime.h>
#include <math.h>
#include <stdint.h>

#define N_NODES 100000
#define N_EDGES 1600000
#define N_QUERY 500000
#define F_IN 7
#define HID 128
#define EMB 64

// ---------------- scratch (device globals) ----------------
__device__ float g_dinv[N_NODES];
__device__ int   g_cnt[N_NODES];
__device__ int   g_off[N_NODES + 1];
__device__ int   g_cur[N_NODES];
__device__ int   g_srcn[N_EDGES];
__device__ float g_bufA[N_NODES * HID];
__device__ float g_bufB[N_NODES * HID];
__device__ float g_bufC[N_NODES * HID];
__device__ float g_z[N_NODES * EMB];
__device__ float g_uv[(size_t)N_NODES * 256];   // [U(128)+b1 | V(128)] per node
__device__ float g_wd1p[64 * 256];              // packed [Wd1_top | Wd1_bot]
__device__ float g_bc[256];                     // [bd1 | 0]
__device__ float g_w2t[64 * 128];               // Wd2 transposed [n][k], tf32-rounded

__device__ __forceinline__ float to_tf32(float x) {
    uint32_t u;
    asm("cvt.rna.tf32.f32 %0, %1;" : "=r"(u) : "f"(x));
    return __uint_as_float(u);
}

// ---------------- CSR build ----------------
__global__ void k_cnt_zero() {
    int i = blockIdx.x * blockDim.x + threadIdx.x;
    if (i < N_NODES) g_cnt[i] = 0;
}

__global__ void k_cnt(const int* __restrict__ ei) {
    int e = blockIdx.x * blockDim.x + threadIdx.x;
    if (e < N_EDGES) atomicAdd(&g_cnt[ei[N_EDGES + e]], 1);
}

__global__ __launch_bounds__(1024) void k_scan() {
    __shared__ int ssum[1024];
    const int tid = threadIdx.x;
    const int CHUNK = (N_NODES + 1023) / 1024;
    int lo = tid * CHUNK;
    int hi = min(lo + CHUNK, N_NODES);
    int sum = 0;
    for (int i = lo; i < hi; i++) sum += g_cnt[i];
    ssum[tid] = sum;
    __syncthreads();
    for (int off = 1; off < 1024; off <<= 1) {
        int t = (tid >= off) ? ssum[tid - off] : 0;
        __syncthreads();
        if (tid >= off) ssum[tid] += t;
        __syncthreads();
    }
    int run = ssum[tid] - sum;
    for (int i = lo; i < hi; i++) {
        g_off[i] = run;
        g_cur[i] = run;
        run += g_cnt[i];
    }
    if (lo < N_NODES && hi == N_NODES) g_off[N_NODES] = run;
}

__global__ void k_dinv() {
    int i = blockIdx.x * blockDim.x + threadIdx.x;
    if (i < N_NODES) g_dinv[i] = rsqrtf((float)g_cnt[i] + 1.0f);
}

__global__ void k_fill(const int* __restrict__ ei) {
    int e = blockIdx.x * blockDim.x + threadIdx.x;
    if (e >= N_EDGES) return;
    int s = ei[e];
    int d = ei[N_EDGES + e];
    int pos = atomicAdd(&g_cur[d], 1);
    g_srcn[pos] = s;
}

// ---------------- pack decoder weights ----------------
__global__ void k_pack(const float* __restrict__ Wd1, const float* __restrict__ bd1,
                       const float* __restrict__ Wd2) {
    int idx = blockIdx.x * blockDim.x + threadIdx.x;
    if (idx < 64 * 256) {
        int k = idx >> 8, j = idx & 255;
        g_wd1p[idx] = (j < 128) ? Wd1[k * 128 + j] : Wd1[(64 + k) * 128 + (j - 128)];
    }
    if (idx < 256) g_bc[idx] = (idx < 128) ? bd1[idx] : 0.f;
    if (idx < 64 * 128) {
        int n = idx >> 7, k = idx & 127;
        g_w2t[idx] = to_tf32(Wd2[k * 64 + n]);
    }
}

// ---------------- layer-1 input matmul: hs1 = (x @ W1) * dinv ----------------
__global__ void k_mm_in(const float* __restrict__ x, const float* __restrict__ W,
                        float* __restrict__ hs) {
    __shared__ float sW[F_IN * HID];
    int tid = threadIdx.x;
    for (int i = tid; i < F_IN * HID; i += blockDim.x) sW[i] = W[i];
    __syncthreads();
    int t = blockIdx.x * blockDim.x + tid;
    if (t >= N_NODES * 32) return;
    int node = t >> 5, j = (t & 31) * 4;
    float xr[F_IN];
#pragma unroll
    for (int k = 0; k < F_IN; k++) xr[k] = x[node * F_IN + k];
    float4 a = make_float4(0.f, 0.f, 0.f, 0.f);
#pragma unroll
    for (int k = 0; k < F_IN; k++) {
        const float* w = &sW[k * HID + j];
        a.x = fmaf(xr[k], w[0], a.x);
        a.y = fmaf(xr[k], w[1], a.y);
        a.z = fmaf(xr[k], w[2], a.z);
        a.w = fmaf(xr[k], w[3], a.w);
    }
    float dv = g_dinv[node];
    ((float4*)hs)[t] = make_float4(a.x * dv, a.y * dv, a.z * dv, a.w * dv);
}

// ---------------- fused CSR aggregation: out = relu(dinv[d]*(sum hs[src] + hs[d]) + b) --
__global__ __launch_bounds__(256) void k_agg(const float* __restrict__ hs,
                                             const float* __restrict__ bias,
                                             float* __restrict__ out) {
    int t = blockIdx.x * blockDim.x + threadIdx.x;
    int node = t >> 5, lane = t & 31;
    if (node >= N_NODES) return;
    const float4* h4 = (const float4*)hs;
    float4 acc = h4[(size_t)node * 32 + lane];
    int e = g_off[node];
    const int end = g_off[node + 1];
    for (; e + 4 <= end; e += 4) {
        int s0 = g_srcn[e], s1 = g_srcn[e + 1], s2 = g_srcn[e + 2], s3 = g_srcn[e + 3];
        float4 v0 = h4[(size_t)s0 * 32 + lane];
        float4 v1 = h4[(size_t)s1 * 32 + lane];
        float4 v2 = h4[(size_t)s2 * 32 + lane];
        float4 v3 = h4[(size_t)s3 * 32 + lane];
        acc.x += v0.x + v1.x + v2.x + v3.x;
        acc.y += v0.y + v1.y + v2.y + v3.y;
        acc.z += v0.z + v1.z + v2.z + v3.z;
        acc.w += v0.w + v1.w + v2.w + v3.w;
    }
    for (; e < end; e++) {
        float4 v0 = h4[(size_t)g_srcn[e] * 32 + lane];
        acc.x += v0.x; acc.y += v0.y; acc.z += v0.z; acc.w += v0.w;
    }
    float dv = g_dinv[node];
    float4 bv = ((const float4*)bias)[lane];
    ((float4*)out)[(size_t)node * 32 + lane] =
        make_float4(fmaxf(fmaf(acc.x, dv, bv.x), 0.f), fmaxf(fmaf(acc.y, dv, bv.y), 0.f),
                    fmaxf(fmaf(acc.z, dv, bv.z), 0.f), fmaxf(fmaf(acc.w, dv, bv.w), 0.f));
}

// ---------------- high-efficiency tiled GEMM: C[M,NT] = A[M,KD] @ B[KD,NT] -------------
template <int MT, int NT, int KD, int EPI>
__global__ __launch_bounds__(256) void gemm_tiled(const float* __restrict__ A,
                                                  const float* __restrict__ B,
                                                  const float* __restrict__ bias,
                                                  float* __restrict__ C) {
    constexpr int TK = 16;
    constexpr int PITCH = MT + 4;
    __shared__ float sAT[TK][PITCH];
    __shared__ float sB[TK][NT];
    const int tid = threadIdx.x;
    const int row0 = blockIdx.x * MT;
    constexpr int NG = NT / 8;
    const int tx = tid % NG;
    const int ty = tid / NG;

    float acc[8][8];
#pragma unroll
    for (int i = 0; i < 8; i++)
#pragma unroll
        for (int j = 0; j < 8; j++) acc[i][j] = 0.f;

    for (int kt = 0; kt < KD; kt += TK) {
#pragma unroll
        for (int l = 0; l < MT * TK / 1024; l++) {
            int idx = tid + l * 256;
            int row = idx >> 2, kq = idx & 3;
            int grow = row0 + row;
            if (grow >= N_NODES) grow = N_NODES - 1;
            float4 v = *(const float4*)&A[(size_t)grow * KD + kt + kq * 4];
            sAT[kq * 4 + 0][row] = v.x;
            sAT[kq * 4 + 1][row] = v.y;
            sAT[kq * 4 + 2][row] = v.z;
            sAT[kq * 4 + 3][row] = v.w;
        }
#pragma unroll
        for (int l = 0; l < TK * NT / 1024; l++) {
            int idx = tid + l * 256;
            int kk = idx / (NT / 4), j4 = idx % (NT / 4);
            *(float4*)&sB[kk][j4 * 4] = *(const float4*)&B[(size_t)(kt + kk) * NT + j4 * 4];
        }
        __syncthreads();
#pragma unroll
        for (int k = 0; k < TK; k++) {
            float4 a0 = *(const float4*)&sAT[k][ty * 8];
            float4 a1 = *(const float4*)&sAT[k][ty * 8 + 4];
            float4 b0 = *(const float4*)&sB[k][tx * 8];
            float4 b1 = *(const float4*)&sB[k][tx * 8 + 4];
            float av[8] = {a0.x, a0.y, a0.z, a0.w, a1.x, a1.y, a1.z, a1.w};
            float bv[8] = {b0.x, b0.y, b0.z, b0.w, b1.x, b1.y, b1.z, b1.w};
#pragma unroll
            for (int i = 0; i < 8; i++)
#pragma unroll
                for (int j = 0; j < 8; j++) acc[i][j] = fmaf(av[i], bv[j], acc[i][j]);
        }
        __syncthreads();
    }

    float bv0[8];
    if (EPI == 1) {
#pragma unroll
        for (int j = 0; j < 8; j++) bv0[j] = bias[tx * 8 + j];
    }
#pragma unroll
    for (int i = 0; i < 8; i++) {
        int row = row0 + ty * 8 + i;
        if (row >= N_NODES) break;
        float r[8];
        if (EPI == 0) {
            float s = g_dinv[row];
#pragma unroll
            for (int j = 0; j < 8; j++) r[j] = acc[i][j] * s;
        } else {
#pragma unroll
            for (int j = 0; j < 8; j++) r[j] = acc[i][j] + bv0[j];
        }
        *(float4*)&C[(size_t)row * NT + tx * 8]     = make_float4(r[0], r[1], r[2], r[3]);
        *(float4*)&C[(size_t)row * NT + tx * 8 + 4] = make_float4(r[4], r[5], r[6], r[7]);
    }
}

// ---------------- decoder: 128 queries/block; tf32 tensor-core stage 2 ------------------
// dyn smem floats: s_d[128][132] | s_w[64][132] | s_c2T[64][132]  = 135168 bytes
__global__ __launch_bounds__(256) void k_decoder(
    const float* __restrict__ uv, const int* __restrict__ qe,
    const float* __restrict__ w2t, const float* __restrict__ bd2,
    const float* __restrict__ Wd3, const float* __restrict__ bd3,
    float* __restrict__ out) {
    extern __shared__ float smem[];
    float* s_d   = smem;                  // [128][132] tf32-rounded activations (q-major)
    float* s_w   = smem + 16896;          // [64][132]  w2T (n-major, tf32)
    float* s_c2T = smem + 25344;          // [64][132]
    __shared__ int s_a[128], s_b[128];
    __shared__ float s_b2[EMB], s_w3[EMB];

    const int tid = threadIdx.x;
    const int q0blk = blockIdx.x * 128;

    // load w2T (tf32 pre-rounded) into smem pitch-132
    for (int i = tid; i < 64 * 128; i += 256) {
        int n = i >> 7, k = i & 127;
        s_w[n * 132 + k] = w2t[i];
    }
    if (tid < EMB) { s_b2[tid] = bd2[tid]; s_w3[tid] = Wd3[tid]; }
    if (tid < 128) {
        int qi = q0blk + tid;
        s_a[tid] = qi < N_QUERY ? qe[qi] : 0;
        s_b[tid] = qi < N_QUERY ? qe[N_QUERY + qi] : 0;
    }
    __syncthreads();

    // stage 1: s_d[q][k] = tf32(relu(U[a_q][k] + V[b_q][k]))
    const float4* uv4 = (const float4*)uv;
    for (int i = tid; i < 128 * 32; i += 256) {
        int q = i >> 5, c4 = i & 31;
        float4 u = uv4[(size_t)s_a[q] * 64 + c4];
        float4 v = uv4[(size_t)s_b[q] * 64 + 32 + c4];
        float* dst = &s_d[q * 132 + c4 * 4];
        dst[0] = to_tf32(fmaxf(u.x + v.x, 0.f));
        dst[1] = to_tf32(fmaxf(u.y + v.y, 0.f));
        dst[2] = to_tf32(fmaxf(u.z + v.z, 0.f));
        dst[3] = to_tf32(fmaxf(u.w + v.w, 0.f));
    }
    __syncthreads();

    // stage 2: c2T = relu(d @ Wd2 + b2) via tf32 mma.m16n8k8; warp = 16-query stripe
    {
        const int lane = tid & 31, warp = tid >> 5;
        const int q0 = warp * 16;
        const int gid = lane >> 2, tig = lane & 3;
        float acc[8][4];
#pragma unroll
        for (int t = 0; t < 8; t++)
#pragma unroll
            for (int j = 0; j < 4; j++) acc[t][j] = 0.f;

#pragma unroll
        for (int k0 = 0; k0 < 128; k0 += 8) {
            float a0 = s_d[(q0 + gid) * 132 + k0 + tig];
            float a1 = s_d[(q0 + gid + 8) * 132 + k0 + tig];
            float a2 = s_d[(q0 + gid) * 132 + k0 + tig + 4];
            float a3 = s_d[(q0 + gid + 8) * 132 + k0 + tig + 4];
#pragma unroll
            for (int t = 0; t < 8; t++) {
                float b0 = s_w[(t * 8 + gid) * 132 + k0 + tig];
                float b1 = s_w[(t * 8 + gid) * 132 + k0 + tig + 4];
                asm volatile(
                    "mma.sync.aligned.m16n8k8.row.col.f32.tf32.tf32.f32 "
                    "{%0,%1,%2,%3}, {%4,%5,%6,%7}, {%8,%9}, {%0,%1,%2,%3};"
                    : "+f"(acc[t][0]), "+f"(acc[t][1]), "+f"(acc[t][2]), "+f"(acc[t][3])
                    : "r"(__float_as_uint(a0)), "r"(__float_as_uint(a1)),
                      "r"(__float_as_uint(a2)), "r"(__float_as_uint(a3)),
                      "r"(__float_as_uint(b0)), "r"(__float_as_uint(b1)));
            }
        }
        // epilogue: bias + relu, store transposed c2T[c][q]
#pragma unroll
        for (int t = 0; t < 8; t++) {
            int c = t * 8 + 2 * tig;
            float bb0 = s_b2[c], bb1 = s_b2[c + 1];
            int qa = q0 + gid, qb = q0 + gid + 8;
            s_c2T[c * 132 + qa]       = fmaxf(acc[t][0] + bb0, 0.f);
            s_c2T[(c + 1) * 132 + qa] = fmaxf(acc[t][1] + bb1, 0.f);
            s_c2T[c * 132 + qb]       = fmaxf(acc[t][2] + bb0, 0.f);
            s_c2T[(c + 1) * 132 + qb] = fmaxf(acc[t][3] + bb1, 0.f);
        }
    }
    __syncthreads();

    // stage 3: logits + sigmoid (conflict-free along q)
    if (tid < 128) {
        int qi = q0blk + tid;
        if (qi < N_QUERY) {
            float s = bd3[0];
#pragma unroll 8
            for (int c = 0; c < EMB; c++) s = fmaf(s_c2T[c * 132 + tid], s_w3[c], s);
            out[qi] = 1.0f / (1.0f + expf(-s));
        }
    }
}

// ---------------- launch ----------------
extern "C" void kernel_launch(void* const* d_in, const int* in_sizes, int n_in,
                              void* d_out, int out_size) {
    const float* x   = (const float*)d_in[0];
    const int* ei    = (const int*)d_in[1];
    const int* qe    = (const int*)d_in[2];
    const float* W1  = (const float*)d_in[3];
    const float* b1  = (const float*)d_in[4];
    const float* W2  = (const float*)d_in[5];
    const float* b2  = (const float*)d_in[6];
    const float* Wfc = (const float*)d_in[7];
    const float* bfc = (const float*)d_in[8];
    const float* Wd1 = (const float*)d_in[9];
    const float* bd1 = (const float*)d_in[10];
    const float* Wd2 = (const float*)d_in[11];
    const float* bd2 = (const float*)d_in[12];
    const float* Wd3 = (const float*)d_in[13];
    const float* bd3 = (const float*)d_in[14];
    float* out = (float*)d_out;

    float *pA, *pB, *pC, *pZ, *pUV, *pW1P, *pBC, *pW2T;
    { void* p; cudaGetSymbolAddress(&p, g_bufA); pA = (float*)p; }
    { void* p; cudaGetSymbolAddress(&p, g_bufB); pB = (float*)p; }
    { void* p; cudaGetSymbolAddress(&p, g_bufC); pC = (float*)p; }
    { void* p; cudaGetSymbolAddress(&p, g_z);    pZ = (float*)p; }
    { void* p; cudaGetSymbolAddress(&p, g_uv);   pUV = (float*)p; }
    { void* p; cudaGetSymbolAddress(&p, g_wd1p); pW1P = (float*)p; }
    { void* p; cudaGetSymbolAddress(&p, g_bc);   pBC = (float*)p; }
    { void* p; cudaGetSymbolAddress(&p, g_w2t);  pW2T = (float*)p; }

    cudaFuncSetAttribute(k_decoder, cudaFuncAttributeMaxDynamicSharedMemorySize, 135168);

    // CSR build + weight packing
    k_cnt_zero<<<(N_NODES + 255) / 256, 256>>>();
    k_cnt<<<(N_EDGES + 255) / 256, 256>>>(ei);
    k_scan<<<1, 1024>>>();
    k_dinv<<<(N_NODES + 255) / 256, 256>>>();
    k_fill<<<(N_EDGES + 255) / 256, 256>>>(ei);
    k_pack<<<64, 256>>>(Wd1, bd1, Wd2);

    // layer 1
    k_mm_in<<<(N_NODES * 32 + 255) / 256, 256>>>(x, W1, pA);
    k_agg<<<(N_NODES * 32 + 255) / 256, 256>>>(pA, b1, pB);

    // layer 2
    gemm_tiled<128, 128, 128, 0><<<(N_NODES + 127) / 128, 256>>>(pB, W2, nullptr, pC);
    k_agg<<<(N_NODES * 32 + 255) / 256, 256>>>(pC, b2, pA);

    // encoder fc
    gemm_tiled<256, 64, 128, 1><<<(N_NODES + 255) / 256, 256>>>(pA, Wfc, bfc, pZ);

    // decoder stage-1 hoist
    gemm_tiled<64, 256, 64, 1><<<(N_NODES + 63) / 64, 256>>>(pZ, pW1P, pBC, pUV);

    // decoder (tf32 tensor-core stage 2)
    k_decoder<<<(N_QUERY + 127) / 128, 256, 135168>>>(pUV, qe, pW2T, bd2, Wd3, bd3, out);
}

// round 7
// speedup vs baseline: 1.8972x; 1.0110x over previous
#include <cuda_runtime.h>
#include <math.h>
#include <stdint.h>

#define N_NODES 100000
#define N_EDGES 1600000
#define N_QUERY 500000
#define F_IN 7
#define HID 128
#define EMB 64

// ---------------- scratch (device globals) ----------------
__device__ float g_dinv[N_NODES];
__device__ int   g_cnt[N_NODES];
__device__ int   g_off[N_NODES + 1];
__device__ int   g_cur[N_NODES];
__device__ int   g_srcn[N_EDGES];
__device__ float g_bufA[N_NODES * HID];
__device__ float g_bufB[N_NODES * HID];
__device__ float g_bufC[N_NODES * HID];
__device__ float g_z[N_NODES * EMB];
__device__ float g_uv[(size_t)N_NODES * 256];   // [U(128)+b1 | V(128)] per node
__device__ float g_wd1p[64 * 256];              // packed [Wd1_top | Wd1_bot]
__device__ float g_bc[256];                     // [bd1 | 0]
__device__ float g_w2t[64 * 128];               // Wd2 transposed [n][k], tf32-rounded

__device__ __forceinline__ float to_tf32(float x) {
    uint32_t u;
    asm("cvt.rna.tf32.f32 %0, %1;" : "=r"(u) : "f"(x));
    return __uint_as_float(u);
}

// ---------------- CSR build ----------------
__global__ void k_cnt_zero() {
    int i = blockIdx.x * blockDim.x + threadIdx.x;
    if (i < N_NODES) g_cnt[i] = 0;
}

__global__ void k_cnt(const int* __restrict__ ei) {
    int e = blockIdx.x * blockDim.x + threadIdx.x;
    if (e < N_EDGES) atomicAdd(&g_cnt[ei[N_EDGES + e]], 1);
}

__global__ __launch_bounds__(1024) void k_scan() {
    __shared__ int ssum[1024];
    const int tid = threadIdx.x;
    const int CHUNK = (N_NODES + 1023) / 1024;
    int lo = tid * CHUNK;
    int hi = min(lo + CHUNK, N_NODES);
    int sum = 0;
    for (int i = lo; i < hi; i++) sum += g_cnt[i];
    ssum[tid] = sum;
    __syncthreads();
    for (int off = 1; off < 1024; off <<= 1) {
        int t = (tid >= off) ? ssum[tid - off] : 0;
        __syncthreads();
        if (tid >= off) ssum[tid] += t;
        __syncthreads();
    }
    int run = ssum[tid] - sum;
    for (int i = lo; i < hi; i++) {
        g_off[i] = run;
        g_cur[i] = run;
        run += g_cnt[i];
    }
    if (lo < N_NODES && hi == N_NODES) g_off[N_NODES] = run;
}

__global__ void k_dinv() {
    int i = blockIdx.x * blockDim.x + threadIdx.x;
    if (i < N_NODES) g_dinv[i] = rsqrtf((float)g_cnt[i] + 1.0f);
}

__global__ void k_fill(const int* __restrict__ ei) {
    int e = blockIdx.x * blockDim.x + threadIdx.x;
    if (e >= N_EDGES) return;
    int s = ei[e];
    int d = ei[N_EDGES + e];
    int pos = atomicAdd(&g_cur[d], 1);
    g_srcn[pos] = s;
}

// ---------------- pack decoder weights ----------------
__global__ void k_pack(const float* __restrict__ Wd1, const float* __restrict__ bd1,
                       const float* __restrict__ Wd2) {
    int idx = blockIdx.x * blockDim.x + threadIdx.x;
    if (idx < 64 * 256) {
        int k = idx >> 8, j = idx & 255;
        g_wd1p[idx] = (j < 128) ? Wd1[k * 128 + j] : Wd1[(64 + k) * 128 + (j - 128)];
    }
    if (idx < 256) g_bc[idx] = (idx < 128) ? bd1[idx] : 0.f;
    if (idx < 64 * 128) {
        int n = idx >> 7, k = idx & 127;
        g_w2t[idx] = to_tf32(Wd2[k * 64 + n]);
    }
}

// ---------------- layer-1 input matmul: hs1 = (x @ W1) * dinv ----------------
__global__ void k_mm_in(const float* __restrict__ x, const float* __restrict__ W,
                        float* __restrict__ hs) {
    __shared__ float sW[F_IN * HID];
    int tid = threadIdx.x;
    for (int i = tid; i < F_IN * HID; i += blockDim.x) sW[i] = W[i];
    __syncthreads();
    int t = blockIdx.x * blockDim.x + tid;
    if (t >= N_NODES * 32) return;
    int node = t >> 5, j = (t & 31) * 4;
    float xr[F_IN];
#pragma unroll
    for (int k = 0; k < F_IN; k++) xr[k] = x[node * F_IN + k];
    float4 a = make_float4(0.f, 0.f, 0.f, 0.f);
#pragma unroll
    for (int k = 0; k < F_IN; k++) {
        const float* w = &sW[k * HID + j];
        a.x = fmaf(xr[k], w[0], a.x);
        a.y = fmaf(xr[k], w[1], a.y);
        a.z = fmaf(xr[k], w[2], a.z);
        a.w = fmaf(xr[k], w[3], a.w);
    }
    float dv = g_dinv[node];
    ((float4*)hs)[t] = make_float4(a.x * dv, a.y * dv, a.z * dv, a.w * dv);
}

// ---------------- fused CSR aggregation: out = relu(dinv[d]*(sum hs[src] + hs[d]) + b) --
__global__ __launch_bounds__(256) void k_agg(const float* __restrict__ hs,
                                             const float* __restrict__ bias,
                                             float* __restrict__ out) {
    int t = blockIdx.x * blockDim.x + threadIdx.x;
    int node = t >> 5, lane = t & 31;
    if (node >= N_NODES) return;
    const float4* h4 = (const float4*)hs;
    float4 acc = h4[(size_t)node * 32 + lane];
    int e = g_off[node];
    const int end = g_off[node + 1];
    for (; e + 4 <= end; e += 4) {
        int s0 = g_srcn[e], s1 = g_srcn[e + 1], s2 = g_srcn[e + 2], s3 = g_srcn[e + 3];
        float4 v0 = h4[(size_t)s0 * 32 + lane];
        float4 v1 = h4[(size_t)s1 * 32 + lane];
        float4 v2 = h4[(size_t)s2 * 32 + lane];
        float4 v3 = h4[(size_t)s3 * 32 + lane];
        acc.x += v0.x + v1.x + v2.x + v3.x;
        acc.y += v0.y + v1.y + v2.y + v3.y;
        acc.z += v0.z + v1.z + v2.z + v3.z;
        acc.w += v0.w + v1.w + v2.w + v3.w;
    }
    for (; e < end; e++) {
        float4 v0 = h4[(size_t)g_srcn[e] * 32 + lane];
        acc.x += v0.x; acc.y += v0.y; acc.z += v0.z; acc.w += v0.w;
    }
    float dv = g_dinv[node];
    float4 bv = ((const float4*)bias)[lane];
    ((float4*)out)[(size_t)node * 32 + lane] =
        make_float4(fmaxf(fmaf(acc.x, dv, bv.x), 0.f), fmaxf(fmaf(acc.y, dv, bv.y), 0.f),
                    fmaxf(fmaf(acc.z, dv, bv.z), 0.f), fmaxf(fmaf(acc.w, dv, bv.w), 0.f));
}

// ---------------- tf32 tensor-core node GEMM: C[M,NT] = A[M,KD] @ B[KD,NT] -------------
// 128-row blocks, 8 warps x 16-row stripes, full-K smem residency, m16n8k8 tf32 mma.
// EPI 0: C = acc * dinv[row];  EPI 1: C = acc + bias[col]
template <int KD, int NT, int EPI>
__global__ __launch_bounds__(256) void gemm_tf32(const float* __restrict__ A,
                                                 const float* __restrict__ B,
                                                 const float* __restrict__ bias,
                                                 float* __restrict__ C) {
    constexpr int PITCH = KD + 4;
    extern __shared__ float sm[];
    float* s_a = sm;                 // [128][PITCH]
    float* s_b = sm + 128 * PITCH;   // [NT][PITCH] (B transposed: [n][k])
    const int tid = threadIdx.x;
    const int row0 = blockIdx.x * 128;

    // B transposed + tf32 (coalesced gmem read)
    for (int i = tid; i < KD * NT; i += 256) {
        int k = i / NT, n = i % NT;
        s_b[n * PITCH + k] = to_tf32(B[i]);
    }
    // A tile + tf32
    for (int i = tid; i < 128 * KD / 4; i += 256) {
        int r = i / (KD / 4), k4 = i % (KD / 4);
        int gr = row0 + r;
        if (gr >= N_NODES) gr = N_NODES - 1;
        float4 v = *(const float4*)&A[(size_t)gr * KD + k4 * 4];
        float* d = &s_a[r * PITCH + k4 * 4];
        d[0] = to_tf32(v.x); d[1] = to_tf32(v.y); d[2] = to_tf32(v.z); d[3] = to_tf32(v.w);
    }
    __syncthreads();

    const int lane = tid & 31, warp = tid >> 5;
    const int q0 = warp * 16;
    const int gid = lane >> 2, tig = lane & 3;
    constexpr int NCHUNK = (NT > 128) ? 2 : 1;
    constexpr int NC = NT / NCHUNK;
    constexpr int NTILES = NC / 8;

    const int qa = row0 + q0 + gid, qb = qa + 8;
    float dva = 1.f, dvb = 1.f;
    if (EPI == 0) {
        dva = (qa < N_NODES) ? g_dinv[qa] : 0.f;
        dvb = (qb < N_NODES) ? g_dinv[qb] : 0.f;
    }

    for (int nc = 0; nc < NCHUNK; nc++) {
        float acc[NTILES][4];
#pragma unroll
        for (int t = 0; t < NTILES; t++)
#pragma unroll
            for (int j = 0; j < 4; j++) acc[t][j] = 0.f;

#pragma unroll
        for (int k0 = 0; k0 < KD; k0 += 8) {
            float a0 = s_a[(q0 + gid) * PITCH + k0 + tig];
            float a1 = s_a[(q0 + gid + 8) * PITCH + k0 + tig];
            float a2 = s_a[(q0 + gid) * PITCH + k0 + tig + 4];
            float a3 = s_a[(q0 + gid + 8) * PITCH + k0 + tig + 4];
#pragma unroll
            for (int t = 0; t < NTILES; t++) {
                float b0 = s_b[(nc * NC + t * 8 + gid) * PITCH + k0 + tig];
                float b1 = s_b[(nc * NC + t * 8 + gid) * PITCH + k0 + tig + 4];
                asm volatile(
                    "mma.sync.aligned.m16n8k8.row.col.f32.tf32.tf32.f32 "
                    "{%0,%1,%2,%3}, {%4,%5,%6,%7}, {%8,%9}, {%0,%1,%2,%3};"
                    : "+f"(acc[t][0]), "+f"(acc[t][1]), "+f"(acc[t][2]), "+f"(acc[t][3])
                    : "r"(__float_as_uint(a0)), "r"(__float_as_uint(a1)),
                      "r"(__float_as_uint(a2)), "r"(__float_as_uint(a3)),
                      "r"(__float_as_uint(b0)), "r"(__float_as_uint(b1)));
            }
        }
#pragma unroll
        for (int t = 0; t < NTILES; t++) {
            int c = nc * NC + t * 8 + 2 * tig;
            float r0, r1, r2, r3;
            if (EPI == 0) {
                r0 = acc[t][0] * dva; r1 = acc[t][1] * dva;
                r2 = acc[t][2] * dvb; r3 = acc[t][3] * dvb;
            } else {
                float b0 = bias[c], b1 = bias[c + 1];
                r0 = acc[t][0] + b0; r1 = acc[t][1] + b1;
                r2 = acc[t][2] + b0; r3 = acc[t][3] + b1;
            }
            if (qa < N_NODES) *(float2*)&C[(size_t)qa * NT + c] = make_float2(r0, r1);
            if (qb < N_NODES) *(float2*)&C[(size_t)qb * NT + c] = make_float2(r2, r3);
        }
    }
}

// ---------------- decoder: 128 queries/block; tf32 tensor-core stage 2 ------------------
// dyn smem floats: s_d[128][132] | s_w[64][132] | s_c2T[64][132]  = 135168 bytes
__global__ __launch_bounds__(256) void k_decoder(
    const float* __restrict__ uv, const int* __restrict__ qe,
    const float* __restrict__ w2t, const float* __restrict__ bd2,
    const float* __restrict__ Wd3, const float* __restrict__ bd3,
    float* __restrict__ out) {
    extern __shared__ float smem[];
    float* s_d   = smem;                  // [128][132] tf32 activations (q-major)
    float* s_w   = smem + 16896;          // [64][132]  w2T (n-major, tf32)
    float* s_c2T = smem + 25344;          // [64][132]
    __shared__ int s_a[128], s_b[128];
    __shared__ float s_b2[EMB], s_w3[EMB];

    const int tid = threadIdx.x;
    const int q0blk = blockIdx.x * 128;

    for (int i = tid; i < 64 * 128; i += 256) {
        int n = i >> 7, k = i & 127;
        s_w[n * 132 + k] = w2t[i];
    }
    if (tid < EMB) { s_b2[tid] = bd2[tid]; s_w3[tid] = Wd3[tid]; }
    if (tid < 128) {
        int qi = q0blk + tid;
        s_a[tid] = qi < N_QUERY ? qe[qi] : 0;
        s_b[tid] = qi < N_QUERY ? qe[N_QUERY + qi] : 0;
    }
    __syncthreads();

    // stage 1: s_d[q][k] = tf32(relu(U[a_q][k] + V[b_q][k]))
    const float4* uv4 = (const float4*)uv;
    for (int i = tid; i < 128 * 32; i += 256) {
        int q = i >> 5, c4 = i & 31;
        float4 u = uv4[(size_t)s_a[q] * 64 + c4];
        float4 v = uv4[(size_t)s_b[q] * 64 + 32 + c4];
        float* dst = &s_d[q * 132 + c4 * 4];
        dst[0] = to_tf32(fmaxf(u.x + v.x, 0.f));
        dst[1] = to_tf32(fmaxf(u.y + v.y, 0.f));
        dst[2] = to_tf32(fmaxf(u.z + v.z, 0.f));
        dst[3] = to_tf32(fmaxf(u.w + v.w, 0.f));
    }
    __syncthreads();

    // stage 2: c2T = relu(d @ Wd2 + b2) via tf32 mma; warp = 16-query stripe
    {
        const int lane = tid & 31, warp = tid >> 5;
        const int q0 = warp * 16;
        const int gid = lane >> 2, tig = lane & 3;
        float acc[8][4];
#pragma unroll
        for (int t = 0; t < 8; t++)
#pragma unroll
            for (int j = 0; j < 4; j++) acc[t][j] = 0.f;

#pragma unroll
        for (int k0 = 0; k0 < 128; k0 += 8) {
            float a0 = s_d[(q0 + gid) * 132 + k0 + tig];
            float a1 = s_d[(q0 + gid + 8) * 132 + k0 + tig];
            float a2 = s_d[(q0 + gid) * 132 + k0 + tig + 4];
            float a3 = s_d[(q0 + gid + 8) * 132 + k0 + tig + 4];
#pragma unroll
            for (int t = 0; t < 8; t++) {
                float b0 = s_w[(t * 8 + gid) * 132 + k0 + tig];
                float b1 = s_w[(t * 8 + gid) * 132 + k0 + tig + 4];
                asm volatile(
                    "mma.sync.aligned.m16n8k8.row.col.f32.tf32.tf32.f32 "
                    "{%0,%1,%2,%3}, {%4,%5,%6,%7}, {%8,%9}, {%0,%1,%2,%3};"
                    : "+f"(acc[t][0]), "+f"(acc[t][1]), "+f"(acc[t][2]), "+f"(acc[t][3])
                    : "r"(__float_as_uint(a0)), "r"(__float_as_uint(a1)),
                      "r"(__float_as_uint(a2)), "r"(__float_as_uint(a3)),
                      "r"(__float_as_uint(b0)), "r"(__float_as_uint(b1)));
            }
        }
#pragma unroll
        for (int t = 0; t < 8; t++) {
            int c = t * 8 + 2 * tig;
            float bb0 = s_b2[c], bb1 = s_b2[c + 1];
            int qa = q0 + gid, qb = q0 + gid + 8;
            s_c2T[c * 132 + qa]       = fmaxf(acc[t][0] + bb0, 0.f);
            s_c2T[(c + 1) * 132 + qa] = fmaxf(acc[t][1] + bb1, 0.f);
            s_c2T[c * 132 + qb]       = fmaxf(acc[t][2] + bb0, 0.f);
            s_c2T[(c + 1) * 132 + qb] = fmaxf(acc[t][3] + bb1, 0.f);
        }
    }
    __syncthreads();

    // stage 3: logits + sigmoid
    if (tid < 128) {
        int qi = q0blk + tid;
        if (qi < N_QUERY) {
            float s = bd3[0];
#pragma unroll 8
            for (int c = 0; c < EMB; c++) s = fmaf(s_c2T[c * 132 + tid], s_w3[c], s);
            out[qi] = 1.0f / (1.0f + expf(-s));
        }
    }
}

// ---------------- launch ----------------
extern "C" void kernel_launch(void* const* d_in, const int* in_sizes, int n_in,
                              void* d_out, int out_size) {
    const float* x   = (const float*)d_in[0];
    const int* ei    = (const int*)d_in[1];
    const int* qe    = (const int*)d_in[2];
    const float* W1  = (const float*)d_in[3];
    const float* b1  = (const float*)d_in[4];
    const float* W2  = (const float*)d_in[5];
    const float* b2  = (const float*)d_in[6];
    const float* Wfc = (const float*)d_in[7];
    const float* bfc = (const float*)d_in[8];
    const float* Wd1 = (const float*)d_in[9];
    const float* bd1 = (const float*)d_in[10];
    const float* Wd2 = (const float*)d_in[11];
    const float* bd2 = (const float*)d_in[12];
    const float* Wd3 = (const float*)d_in[13];
    const float* bd3 = (const float*)d_in[14];
    float* out = (float*)d_out;

    float *pA, *pB, *pC, *pZ, *pUV, *pW1P, *pBC, *pW2T;
    { void* p; cudaGetSymbolAddress(&p, g_bufA); pA = (float*)p; }
    { void* p; cudaGetSymbolAddress(&p, g_bufB); pB = (float*)p; }
    { void* p; cudaGetSymbolAddress(&p, g_bufC); pC = (float*)p; }
    { void* p; cudaGetSymbolAddress(&p, g_z);    pZ = (float*)p; }
    { void* p; cudaGetSymbolAddress(&p, g_uv);   pUV = (float*)p; }
    { void* p; cudaGetSymbolAddress(&p, g_wd1p); pW1P = (float*)p; }
    { void* p; cudaGetSymbolAddress(&p, g_bc);   pBC = (float*)p; }
    { void* p; cudaGetSymbolAddress(&p, g_w2t);  pW2T = (float*)p; }

    // dynamic smem sizes
    const int SM_L2 = (128 * 132 + 128 * 132) * 4;  // 135168
    const int SM_FC = (128 * 132 + 64 * 132) * 4;   // 101376
    const int SM_UV = (128 * 68 + 256 * 68) * 4;    // 104448
    cudaFuncSetAttribute(gemm_tf32<128, 128, 0>, cudaFuncAttributeMaxDynamicSharedMemorySize, SM_L2);
    cudaFuncSetAttribute(gemm_tf32<128, 64, 1>,  cudaFuncAttributeMaxDynamicSharedMemorySize, SM_FC);
    cudaFuncSetAttribute(gemm_tf32<64, 256, 1>,  cudaFuncAttributeMaxDynamicSharedMemorySize, SM_UV);
    cudaFuncSetAttribute(k_decoder, cudaFuncAttributeMaxDynamicSharedMemorySize, 135168);

    const int NBLK = (N_NODES + 127) / 128;

    // CSR build + weight packing
    k_cnt_zero<<<(N_NODES + 255) / 256, 256>>>();
    k_cnt<<<(N_EDGES + 255) / 256, 256>>>(ei);
    k_scan<<<1, 1024>>>();
    k_dinv<<<(N_NODES + 255) / 256, 256>>>();
    k_fill<<<(N_EDGES + 255) / 256, 256>>>(ei);
    k_pack<<<64, 256>>>(Wd1, bd1, Wd2);

    // layer 1
    k_mm_in<<<(N_NODES * 32 + 255) / 256, 256>>>(x, W1, pA);
    k_agg<<<(N_NODES * 32 + 255) / 256, 256>>>(pA, b1, pB);

    // layer 2 (tf32 tensor cores): hs2 = (pB@W2)*dinv -> pC
    gemm_tf32<128, 128, 0><<<NBLK, 256, SM_L2>>>(pB, W2, nullptr, pC);
    k_agg<<<(N_NODES * 32 + 255) / 256, 256>>>(pC, b2, pA);

    // encoder fc (tf32): z = pA@Wfc + bfc -> pZ
    gemm_tf32<128, 64, 1><<<NBLK, 256, SM_FC>>>(pA, Wfc, bfc, pZ);

    // decoder stage-1 hoist (tf32): UV = z @ [Wd1_top|Wd1_bot] + [bd1|0]
    gemm_tf32<64, 256, 1><<<NBLK, 256, SM_UV>>>(pZ, pW1P, pBC, pUV);

    // decoder (tf32 stage 2)
    k_decoder<<<(N_QUERY + 127) / 128, 256, 135168>>>(pUV, qe, pW2T, bd2, Wd3, bd3, out);
}

// round 8
// speedup vs baseline: 2.1459x; 1.1311x over previous
#include <cuda_runtime.h>
#include <cuda_bf16.h>
#include <math.h>
#include <stdint.h>

#define N_NODES 100000
#define N_EDGES 1600000
#define N_QUERY 500000
#define F_IN 7
#define HID 128
#define EMB 64

// ---------------- scratch (device globals) ----------------
__device__ float g_dinv[N_NODES];
__device__ int   g_cnt[N_NODES];
__device__ int   g_off[N_NODES + 1];
__device__ int   g_cur[N_NODES];
__device__ int   g_srcn[N_EDGES];
__device__ __nv_bfloat16 g_hsb[(size_t)N_NODES * HID];   // bf16 message buffer (both layers)
__device__ float g_bufA[N_NODES * HID];                  // fp32 aggregated activations
__device__ float g_z[N_NODES * EMB];
__device__ __nv_bfloat16 g_uvb[(size_t)N_NODES * 256];   // bf16 [U(128)+b1 | V(128)]
__device__ float g_wd1p[64 * 256];                       // packed [Wd1_top | Wd1_bot]
__device__ float g_bc[256];                              // [bd1 | 0]
__device__ float g_w2t[64 * 128];                        // Wd2^T [n][k], tf32-rounded

__device__ __forceinline__ float to_tf32(float x) {
    uint32_t u;
    asm("cvt.rna.tf32.f32 %0, %1;" : "=r"(u) : "f"(x));
    return __uint_as_float(u);
}

// ---------------- CSR build ----------------
__global__ void k_cnt_zero() {
    int i = blockIdx.x * blockDim.x + threadIdx.x;
    if (i < N_NODES) g_cnt[i] = 0;
}

__global__ void k_cnt(const int* __restrict__ ei) {
    int e = blockIdx.x * blockDim.x + threadIdx.x;
    if (e < N_EDGES) atomicAdd(&g_cnt[ei[N_EDGES + e]], 1);
}

__global__ __launch_bounds__(1024) void k_scan() {
    __shared__ int ssum[1024];
    const int tid = threadIdx.x;
    const int CHUNK = (N_NODES + 1023) / 1024;
    int lo = tid * CHUNK;
    int hi = min(lo + CHUNK, N_NODES);
    int sum = 0;
    for (int i = lo; i < hi; i++) sum += g_cnt[i];
    ssum[tid] = sum;
    __syncthreads();
    for (int off = 1; off < 1024; off <<= 1) {
        int t = (tid >= off) ? ssum[tid - off] : 0;
        __syncthreads();
        if (tid >= off) ssum[tid] += t;
        __syncthreads();
    }
    int run = ssum[tid] - sum;
    for (int i = lo; i < hi; i++) {
        g_off[i] = run;
        g_cur[i] = run;
        run += g_cnt[i];
    }
    if (lo < N_NODES && hi == N_NODES) g_off[N_NODES] = run;
}

__global__ void k_dinv() {
    int i = blockIdx.x * blockDim.x + threadIdx.x;
    if (i < N_NODES) g_dinv[i] = rsqrtf((float)g_cnt[i] + 1.0f);
}

__global__ void k_fill(const int* __restrict__ ei) {
    int e = blockIdx.x * blockDim.x + threadIdx.x;
    if (e >= N_EDGES) return;
    int s = ei[e];
    int d = ei[N_EDGES + e];
    int pos = atomicAdd(&g_cur[d], 1);
    g_srcn[pos] = s;
}

// ---------------- pack decoder weights ----------------
__global__ void k_pack(const float* __restrict__ Wd1, const float* __restrict__ bd1,
                       const float* __restrict__ Wd2) {
    int idx = blockIdx.x * blockDim.x + threadIdx.x;
    if (idx < 64 * 256) {
        int k = idx >> 8, j = idx & 255;
        g_wd1p[idx] = (j < 128) ? Wd1[k * 128 + j] : Wd1[(64 + k) * 128 + (j - 128)];
    }
    if (idx < 256) g_bc[idx] = (idx < 128) ? bd1[idx] : 0.f;
    if (idx < 64 * 128) {
        int n = idx >> 7, k = idx & 127;
        g_w2t[idx] = to_tf32(Wd2[k * 64 + n]);
    }
}

// ---------------- layer-1 input matmul: hs1 = bf16((x @ W1) * dinv) ----------------
__global__ void k_mm_in(const float* __restrict__ x, const float* __restrict__ W,
                        __nv_bfloat16* __restrict__ hs) {
    __shared__ float sW[F_IN * HID];
    int tid = threadIdx.x;
    for (int i = tid; i < F_IN * HID; i += blockDim.x) sW[i] = W[i];
    __syncthreads();
    int t = blockIdx.x * blockDim.x + tid;
    if (t >= N_NODES * 32) return;
    int node = t >> 5, j = (t & 31) * 4;
    float xr[F_IN];
#pragma unroll
    for (int k = 0; k < F_IN; k++) xr[k] = x[node * F_IN + k];
    float4 a = make_float4(0.f, 0.f, 0.f, 0.f);
#pragma unroll
    for (int k = 0; k < F_IN; k++) {
        const float* w = &sW[k * HID + j];
        a.x = fmaf(xr[k], w[0], a.x);
        a.y = fmaf(xr[k], w[1], a.y);
        a.z = fmaf(xr[k], w[2], a.z);
        a.w = fmaf(xr[k], w[3], a.w);
    }
    float dv = g_dinv[node];
    __nv_bfloat162 p0 = __floats2bfloat162_rn(a.x * dv, a.y * dv);
    __nv_bfloat162 p1 = __floats2bfloat162_rn(a.z * dv, a.w * dv);
    uint2 o;
    o.x = *(uint32_t*)&p0;
    o.y = *(uint32_t*)&p1;
    ((uint2*)hs)[t] = o;
}

// ---------------- fused CSR aggregation (bf16 gather): out = relu(dinv*(sum+self)+b) ----
__global__ __launch_bounds__(256) void k_agg(const __nv_bfloat16* __restrict__ hs,
                                             const float* __restrict__ bias,
                                             float* __restrict__ out) {
    int t = blockIdx.x * blockDim.x + threadIdx.x;
    int node = t >> 5, lane = t & 31;
    if (node >= N_NODES) return;
    const uint2* h2 = (const uint2*)hs;   // 32 uint2 per row (128 bf16)

    float ax, ay, az, aw;
    {
        uint2 v = h2[(size_t)node * 32 + lane];
        float2 f0 = __bfloat1622float2(*(__nv_bfloat162*)&v.x);
        float2 f1 = __bfloat1622float2(*(__nv_bfloat162*)&v.y);
        ax = f0.x; ay = f0.y; az = f1.x; aw = f1.y;
    }
    int e = g_off[node];
    const int end = g_off[node + 1];
    for (; e + 4 <= end; e += 4) {
        int s0 = g_srcn[e], s1 = g_srcn[e + 1], s2 = g_srcn[e + 2], s3 = g_srcn[e + 3];
        uint2 v0 = h2[(size_t)s0 * 32 + lane];
        uint2 v1 = h2[(size_t)s1 * 32 + lane];
        uint2 v2 = h2[(size_t)s2 * 32 + lane];
        uint2 v3 = h2[(size_t)s3 * 32 + lane];
        float2 a0 = __bfloat1622float2(*(__nv_bfloat162*)&v0.x);
        float2 b0 = __bfloat1622float2(*(__nv_bfloat162*)&v0.y);
        float2 a1 = __bfloat1622float2(*(__nv_bfloat162*)&v1.x);
        float2 b1 = __bfloat1622float2(*(__nv_bfloat162*)&v1.y);
        float2 a2 = __bfloat1622float2(*(__nv_bfloat162*)&v2.x);
        float2 b2 = __bfloat1622float2(*(__nv_bfloat162*)&v2.y);
        float2 a3 = __bfloat1622float2(*(__nv_bfloat162*)&v3.x);
        float2 b3 = __bfloat1622float2(*(__nv_bfloat162*)&v3.y);
        ax += a0.x + a1.x + a2.x + a3.x;
        ay += a0.y + a1.y + a2.y + a3.y;
        az += b0.x + b1.x + b2.x + b3.x;
        aw += b0.y + b1.y + b2.y + b3.y;
    }
    for (; e < end; e++) {
        uint2 v = h2[(size_t)g_srcn[e] * 32 + lane];
        float2 f0 = __bfloat1622float2(*(__nv_bfloat162*)&v.x);
        float2 f1 = __bfloat1622float2(*(__nv_bfloat162*)&v.y);
        ax += f0.x; ay += f0.y; az += f1.x; aw += f1.y;
    }
    float dv = g_dinv[node];
    float4 bv = ((const float4*)bias)[lane];
    ((float4*)out)[(size_t)node * 32 + lane] =
        make_float4(fmaxf(fmaf(ax, dv, bv.x), 0.f), fmaxf(fmaf(ay, dv, bv.y), 0.f),
                    fmaxf(fmaf(az, dv, bv.z), 0.f), fmaxf(fmaf(aw, dv, bv.w), 0.f));
}

// ---------------- tf32 tensor-core node GEMM: C[M,NT] = A[M,KD] @ B[KD,NT] -------------
// EPI 0: C = acc * dinv[row];  EPI 1: C = acc + bias[col].  OUT_BF16 selects output type.
template <int KD, int NT, int EPI, bool OUT_BF16>
__global__ __launch_bounds__(256) void gemm_tf32(const float* __restrict__ A,
                                                 const float* __restrict__ B,
                                                 const float* __restrict__ bias,
                                                 void* __restrict__ Cv) {
    constexpr int PITCH = KD + 4;
    extern __shared__ float sm[];
    float* s_a = sm;                 // [128][PITCH]
    float* s_b = sm + 128 * PITCH;   // [NT][PITCH] (B transposed: [n][k])
    const int tid = threadIdx.x;
    const int row0 = blockIdx.x * 128;

    for (int i = tid; i < KD * NT; i += 256) {
        int k = i / NT, n = i % NT;
        s_b[n * PITCH + k] = to_tf32(B[i]);
    }
    for (int i = tid; i < 128 * KD / 4; i += 256) {
        int r = i / (KD / 4), k4 = i % (KD / 4);
        int gr = row0 + r;
        if (gr >= N_NODES) gr = N_NODES - 1;
        float4 v = *(const float4*)&A[(size_t)gr * KD + k4 * 4];
        float* d = &s_a[r * PITCH + k4 * 4];
        d[0] = to_tf32(v.x); d[1] = to_tf32(v.y); d[2] = to_tf32(v.z); d[3] = to_tf32(v.w);
    }
    __syncthreads();

    const int lane = tid & 31, warp = tid >> 5;
    const int q0 = warp * 16;
    const int gid = lane >> 2, tig = lane & 3;
    constexpr int NCHUNK = (NT > 128) ? 2 : 1;
    constexpr int NC = NT / NCHUNK;
    constexpr int NTILES = NC / 8;

    const int qa = row0 + q0 + gid, qb = qa + 8;
    float dva = 1.f, dvb = 1.f;
    if (EPI == 0) {
        dva = (qa < N_NODES) ? g_dinv[qa] : 0.f;
        dvb = (qb < N_NODES) ? g_dinv[qb] : 0.f;
    }

    for (int nc = 0; nc < NCHUNK; nc++) {
        float acc[NTILES][4];
#pragma unroll
        for (int t = 0; t < NTILES; t++)
#pragma unroll
            for (int j = 0; j < 4; j++) acc[t][j] = 0.f;

#pragma unroll
        for (int k0 = 0; k0 < KD; k0 += 8) {
            float a0 = s_a[(q0 + gid) * PITCH + k0 + tig];
            float a1 = s_a[(q0 + gid + 8) * PITCH + k0 + tig];
            float a2 = s_a[(q0 + gid) * PITCH + k0 + tig + 4];
            float a3 = s_a[(q0 + gid + 8) * PITCH + k0 + tig + 4];
#pragma unroll
            for (int t = 0; t < NTILES; t++) {
                float b0 = s_b[(nc * NC + t * 8 + gid) * PITCH + k0 + tig];
                float b1 = s_b[(nc * NC + t * 8 + gid) * PITCH + k0 + tig + 4];
                asm volatile(
                    "mma.sync.aligned.m16n8k8.row.col.f32.tf32.tf32.f32 "
                    "{%0,%1,%2,%3}, {%4,%5,%6,%7}, {%8,%9}, {%0,%1,%2,%3};"
                    : "+f"(acc[t][0]), "+f"(acc[t][1]), "+f"(acc[t][2]), "+f"(acc[t][3])
                    : "r"(__float_as_uint(a0)), "r"(__float_as_uint(a1)),
                      "r"(__float_as_uint(a2)), "r"(__float_as_uint(a3)),
                      "r"(__float_as_uint(b0)), "r"(__float_as_uint(b1)));
            }
        }
#pragma unroll
        for (int t = 0; t < NTILES; t++) {
            int c = nc * NC + t * 8 + 2 * tig;
            float r0, r1, r2, r3;
            if (EPI == 0) {
                r0 = acc[t][0] * dva; r1 = acc[t][1] * dva;
                r2 = acc[t][2] * dvb; r3 = acc[t][3] * dvb;
            } else {
                float b0 = bias[c], b1 = bias[c + 1];
                r0 = acc[t][0] + b0; r1 = acc[t][1] + b1;
                r2 = acc[t][2] + b0; r3 = acc[t][3] + b1;
            }
            if (OUT_BF16) {
                __nv_bfloat16* C = (__nv_bfloat16*)Cv;
                __nv_bfloat162 pa = __floats2bfloat162_rn(r0, r1);
                __nv_bfloat162 pb = __floats2bfloat162_rn(r2, r3);
                if (qa < N_NODES) *(__nv_bfloat162*)&C[(size_t)qa * NT + c] = pa;
                if (qb < N_NODES) *(__nv_bfloat162*)&C[(size_t)qb * NT + c] = pb;
            } else {
                float* C = (float*)Cv;
                if (qa < N_NODES) *(float2*)&C[(size_t)qa * NT + c] = make_float2(r0, r1);
                if (qb < N_NODES) *(float2*)&C[(size_t)qb * NT + c] = make_float2(r2, r3);
            }
        }
    }
}

// ---------------- decoder: 128 queries/block; bf16 UV gather, tf32 TC stage 2 -----------
// dyn smem floats: s_d[128][132] | s_w[64][132] | s_c2T[64][132]  = 135168 bytes
__global__ __launch_bounds__(256) void k_decoder(
    const __nv_bfloat16* __restrict__ uv, const int* __restrict__ qe,
    const float* __restrict__ w2t, const float* __restrict__ bd2,
    const float* __restrict__ Wd3, const float* __restrict__ bd3,
    float* __restrict__ out) {
    extern __shared__ float smem[];
    float* s_d   = smem;                  // [128][132] tf32 activations (q-major)
    float* s_w   = smem + 16896;          // [64][132]  w2T (n-major, tf32)
    float* s_c2T = smem + 25344;          // [64][132]
    __shared__ int s_a[128], s_b[128];
    __shared__ float s_b2[EMB], s_w3[EMB];

    const int tid = threadIdx.x;
    const int q0blk = blockIdx.x * 128;

    for (int i = tid; i < 64 * 128; i += 256) {
        int n = i >> 7, k = i & 127;
        s_w[n * 132 + k] = w2t[i];
    }
    if (tid < EMB) { s_b2[tid] = bd2[tid]; s_w3[tid] = Wd3[tid]; }
    if (tid < 128) {
        int qi = q0blk + tid;
        s_a[tid] = qi < N_QUERY ? qe[qi] : 0;
        s_b[tid] = qi < N_QUERY ? qe[N_QUERY + qi] : 0;
    }
    __syncthreads();

    // stage 1: s_d[q][k] = tf32(relu(U[a_q][k] + V[b_q][k]))  (bf16 gather)
    const uint2* uv2 = (const uint2*)uv;  // 64 uint2 per 256-entry row
    for (int i = tid; i < 128 * 32; i += 256) {
        int q = i >> 5, c = i & 31;
        uint2 uu = uv2[(size_t)s_a[q] * 64 + c];
        uint2 vv = uv2[(size_t)s_b[q] * 64 + 32 + c];
        float2 u0 = __bfloat1622float2(*(__nv_bfloat162*)&uu.x);
        float2 u1 = __bfloat1622float2(*(__nv_bfloat162*)&uu.y);
        float2 v0 = __bfloat1622float2(*(__nv_bfloat162*)&vv.x);
        float2 v1 = __bfloat1622float2(*(__nv_bfloat162*)&vv.y);
        float* dst = &s_d[q * 132 + c * 4];
        dst[0] = to_tf32(fmaxf(u0.x + v0.x, 0.f));
        dst[1] = to_tf32(fmaxf(u0.y + v0.y, 0.f));
        dst[2] = to_tf32(fmaxf(u1.x + v1.x, 0.f));
        dst[3] = to_tf32(fmaxf(u1.y + v1.y, 0.f));
    }
    __syncthreads();

    // stage 2: c2T = relu(d @ Wd2 + b2) via tf32 mma; warp = 16-query stripe
    {
        const int lane = tid & 31, warp = tid >> 5;
        const int q0 = warp * 16;
        const int gid = lane >> 2, tig = lane & 3;
        float acc[8][4];
#pragma unroll
        for (int t = 0; t < 8; t++)
#pragma unroll
            for (int j = 0; j < 4; j++) acc[t][j] = 0.f;

#pragma unroll
        for (int k0 = 0; k0 < 128; k0 += 8) {
            float a0 = s_d[(q0 + gid) * 132 + k0 + tig];
            float a1 = s_d[(q0 + gid + 8) * 132 + k0 + tig];
            float a2 = s_d[(q0 + gid) * 132 + k0 + tig + 4];
            float a3 = s_d[(q0 + gid + 8) * 132 + k0 + tig + 4];
#pragma unroll
            for (int t = 0; t < 8; t++) {
                float b0 = s_w[(t * 8 + gid) * 132 + k0 + tig];
                float b1 = s_w[(t * 8 + gid) * 132 + k0 + tig + 4];
                asm volatile(
                    "mma.sync.aligned.m16n8k8.row.col.f32.tf32.tf32.f32 "
                    "{%0,%1,%2,%3}, {%4,%5,%6,%7}, {%8,%9}, {%0,%1,%2,%3};"
                    : "+f"(acc[t][0]), "+f"(acc[t][1]), "+f"(acc[t][2]), "+f"(acc[t][3])
                    : "r"(__float_as_uint(a0)), "r"(__float_as_uint(a1)),
                      "r"(__float_as_uint(a2)), "r"(__float_as_uint(a3)),
                      "r"(__float_as_uint(b0)), "r"(__float_as_uint(b1)));
            }
        }
#pragma unroll
        for (int t = 0; t < 8; t++) {
            int c = t * 8 + 2 * tig;
            float bb0 = s_b2[c], bb1 = s_b2[c + 1];
            int qa = q0 + gid, qb = q0 + gid + 8;
            s_c2T[c * 132 + qa]       = fmaxf(acc[t][0] + bb0, 0.f);
            s_c2T[(c + 1) * 132 + qa] = fmaxf(acc[t][1] + bb1, 0.f);
            s_c2T[c * 132 + qb]       = fmaxf(acc[t][2] + bb0, 0.f);
            s_c2T[(c + 1) * 132 + qb] = fmaxf(acc[t][3] + bb1, 0.f);
        }
    }
    __syncthreads();

    // stage 3: logits + sigmoid
    if (tid < 128) {
        int qi = q0blk + tid;
        if (qi < N_QUERY) {
            float s = bd3[0];
#pragma unroll 8
            for (int c = 0; c < EMB; c++) s = fmaf(s_c2T[c * 132 + tid], s_w3[c], s);
            out[qi] = 1.0f / (1.0f + expf(-s));
        }
    }
}

// ---------------- launch ----------------
extern "C" void kernel_launch(void* const* d_in, const int* in_sizes, int n_in,
                              void* d_out, int out_size) {
    const float* x   = (const float*)d_in[0];
    const int* ei    = (const int*)d_in[1];
    const int* qe    = (const int*)d_in[2];
    const float* W1  = (const float*)d_in[3];
    const float* b1  = (const float*)d_in[4];
    const float* W2  = (const float*)d_in[5];
    const float* b2  = (const float*)d_in[6];
    const float* Wfc = (const float*)d_in[7];
    const float* bfc = (const float*)d_in[8];
    const float* Wd1 = (const float*)d_in[9];
    const float* bd1 = (const float*)d_in[10];
    const float* Wd2 = (const float*)d_in[11];
    const float* bd2 = (const float*)d_in[12];
    const float* Wd3 = (const float*)d_in[13];
    const float* bd3 = (const float*)d_in[14];
    float* out = (float*)d_out;

    float *pA, *pZ, *pW1P, *pBC, *pW2T;
    __nv_bfloat16 *pHS, *pUV;
    { void* p; cudaGetSymbolAddress(&p, g_bufA); pA = (float*)p; }
    { void* p; cudaGetSymbolAddress(&p, g_z);    pZ = (float*)p; }
    { void* p; cudaGetSymbolAddress(&p, g_hsb);  pHS = (__nv_bfloat16*)p; }
    { void* p; cudaGetSymbolAddress(&p, g_uvb);  pUV = (__nv_bfloat16*)p; }
    { void* p; cudaGetSymbolAddress(&p, g_wd1p); pW1P = (float*)p; }
    { void* p; cudaGetSymbolAddress(&p, g_bc);   pBC = (float*)p; }
    { void* p; cudaGetSymbolAddress(&p, g_w2t);  pW2T = (float*)p; }

    const int SM_L2 = (128 * 132 + 128 * 132) * 4;  // 135168
    const int SM_FC = (128 * 132 + 64 * 132) * 4;   // 101376
    const int SM_UV = (128 * 68 + 256 * 68) * 4;    // 104448
    cudaFuncSetAttribute(gemm_tf32<128, 128, 0, true>,  cudaFuncAttributeMaxDynamicSharedMemorySize, SM_L2);
    cudaFuncSetAttribute(gemm_tf32<128, 64, 1, false>,  cudaFuncAttributeMaxDynamicSharedMemorySize, SM_FC);
    cudaFuncSetAttribute(gemm_tf32<64, 256, 1, true>,   cudaFuncAttributeMaxDynamicSharedMemorySize, SM_UV);
    cudaFuncSetAttribute(k_decoder, cudaFuncAttributeMaxDynamicSharedMemorySize, 135168);

    const int NBLK = (N_NODES + 127) / 128;

    // CSR build + weight packing
    k_cnt_zero<<<(N_NODES + 255) / 256, 256>>>();
    k_cnt<<<(N_EDGES + 255) / 256, 256>>>(ei);
    k_scan<<<1, 1024>>>();
    k_dinv<<<(N_NODES + 255) / 256, 256>>>();
    k_fill<<<(N_EDGES + 255) / 256, 256>>>(ei);
    k_pack<<<64, 256>>>(Wd1, bd1, Wd2);

    // layer 1: hs1(bf16) -> agg -> h1'(fp32)
    k_mm_in<<<(N_NODES * 32 + 255) / 256, 256>>>(x, W1, pHS);
    k_agg<<<(N_NODES * 32 + 255) / 256, 256>>>(pHS, b1, pA);

    // layer 2: hs2 = bf16((h1'@W2)*dinv) -> agg -> h2'(fp32)
    gemm_tf32<128, 128, 0, true><<<NBLK, 256, SM_L2>>>(pA, W2, nullptr, pHS);
    k_agg<<<(N_NODES * 32 + 255) / 256, 256>>>(pHS, b2, pA);

    // encoder fc: z = h2'@Wfc + bfc (fp32)
    gemm_tf32<128, 64, 1, false><<<NBLK, 256, SM_FC>>>(pA, Wfc, bfc, pZ);

    // decoder stage-1 hoist: UV = bf16(z @ [Wd1_top|Wd1_bot] + [bd1|0])
    gemm_tf32<64, 256, 1, true><<<NBLK, 256, SM_UV>>>(pZ, pW1P, pBC, pUV);

    // decoder (bf16 gather + tf32 TC stage 2)
    k_decoder<<<(N_QUERY + 127) / 128, 256, 135168>>>(pUV, qe, pW2T, bd2, Wd3, bd3, out);
}